// round 8
// baseline (speedup 1.0000x reference)
#include <cuda_runtime.h>
#include <cuda_bf16.h>
#include <math.h>
#include <stdint.h>

// ---------------------------------------------------------------------------
// Problem constants
// ---------------------------------------------------------------------------
#define BB 2
#define SS 1024
#define WW 64
#define PP (SS + WW - 1)   // 1087
#define EE 256
#define FIN 64
#define FF 1024
#define TE 768
#define NH 8
#define HD 32
#define NWIN (BB * SS)     // 2048
#define NROW (NWIN * WW)   // 131072
#define OUTD 10
#define LN_EPS 1e-5f
#define ATT_SCALE 0.17677669529663687f

// ---------------------------------------------------------------------------
// Scratch
// ---------------------------------------------------------------------------
__device__ float g_emb  [BB * PP * EE];
__device__ float g_qkv  [BB * PP * TE];
__device__ float g_bufA [(size_t)NROW * EE];
__device__ float g_bufB [(size_t)NROW * EE];
__device__ float g_bufC [(size_t)NROW * FF];   // FFN hidden; later KV2 (stride 512)
__device__ float g_xlast[NWIN * EE];
__device__ float g_r1   [NWIN * EE];
__device__ float g_r2   [NWIN * EE];
__device__ float g_r3   [NWIN * FF];

// ---------------------------------------------------------------------------
// Common MMA helpers
// ---------------------------------------------------------------------------
__device__ __forceinline__ uint32_t f2tf(float f) {
    uint32_t r;
    asm("cvt.rna.tf32.f32 %0, %1;" : "=r"(r) : "f"(f));
    return r;
}

__device__ __forceinline__ void mma_tf32(float* c, const uint32_t* a, const uint32_t* b) {
    asm volatile(
        "mma.sync.aligned.m16n8k8.row.col.f32.tf32.tf32.f32 "
        "{%0,%1,%2,%3},{%4,%5,%6,%7},{%8,%9},{%0,%1,%2,%3};"
        : "+f"(c[0]), "+f"(c[1]), "+f"(c[2]), "+f"(c[3])
        : "r"(a[0]), "r"(a[1]), "r"(a[2]), "r"(a[3]), "r"(b[0]), "r"(b[1]));
}

__device__ __forceinline__ void cp16(void* s, const void* g) {
    uint32_t sa = (uint32_t)__cvta_generic_to_shared(s);
    asm volatile("cp.async.cg.shared.global [%0], [%1], 16;" :: "r"(sa), "l"(g));
}

// in-place tf32-round 4 consecutive floats in smem
__device__ __forceinline__ void cvt4(float* p) {
    float4 v = *(float4*)p;
    uint4 u;
    u.x = f2tf(v.x); u.y = f2tf(v.y); u.z = f2tf(v.z); u.w = f2tf(v.w);
    *(uint4*)p = u;
}

// ---------------------------------------------------------------------------
// TF32 tensor-core GEMM (NT): C[m,n] = act(sum_k A[m,k]*B[n,k] + bias[n])
// 128x128 tile, BK=16, 2-stage cp.async (prefetch AFTER barrier -> race-free).
// Conversion to tf32 done ONCE per tile in smem (each thread converts the 16
// floats it copied), so the MMA loop issues zero cvt instructions.
// Requires: K % 16 == 0, N % 128 == 0. act: 0 none, 1 silu.
// ---------------------------------------------------------------------------
#define TBK 16
#define SMS 20   // smem row stride (16 + 4 pad)

__global__ __launch_bounds__(256) void tgemm(
    const float* __restrict__ A, const float* __restrict__ B,
    const float* __restrict__ bias, float* __restrict__ C,
    int M, int N, int K, int lda, int ldb, int ldc, int act) {
    __shared__ __align__(16) float As[2][128][SMS];
    __shared__ __align__(16) float Bs[2][128][SMS];
    const int tid = threadIdx.x;
    const int bm = blockIdx.y * 128, bn = blockIdx.x * 128;
    const int lane = tid & 31, wid = tid >> 5;
    const int wm = (wid >> 2) * 64, wn = (wid & 3) * 32;
    const int g = lane >> 2, t4 = lane & 3;

    float acc[4][4][4];
#pragma unroll
    for (int i = 0; i < 4; i++)
#pragma unroll
        for (int j = 0; j < 4; j++)
#pragma unroll
            for (int k = 0; k < 4; k++) acc[i][j][k] = 0.f;

    const int T = K / TBK;
    const int r0i = tid >> 2, c4i = (tid & 3) << 2;
    const int r1i = (tid + 256) >> 2, c4i2 = ((tid + 256) & 3) << 2;
    int gcl0 = bm + r0i; if (gcl0 >= M) gcl0 = M - 1;
    int gcl1 = bm + r1i; if (gcl1 >= M) gcl1 = M - 1;

    // prologue: tile 0
    cp16(&As[0][r0i][c4i],  A + (size_t)gcl0 * lda + c4i);
    cp16(&As[0][r1i][c4i2], A + (size_t)gcl1 * lda + c4i2);
    cp16(&Bs[0][r0i][c4i],  B + (size_t)(bn + r0i) * ldb + c4i);
    cp16(&Bs[0][r1i][c4i2], B + (size_t)(bn + r1i) * ldb + c4i2);
    asm volatile("cp.async.commit_group;");

    for (int t = 0; t < T; t++) {
        const int cur = t & 1;
        asm volatile("cp.async.wait_group 0;");
        // convert the 16 floats this thread copied (visible after wait)
        cvt4(&As[cur][r0i][c4i]);
        cvt4(&As[cur][r1i][c4i2]);
        cvt4(&Bs[cur][r0i][c4i]);
        cvt4(&Bs[cur][r1i][c4i2]);
        __syncthreads();
        if (t + 1 < T) {
            const int k0 = (t + 1) * TBK;
            const int nxt = cur ^ 1;
            cp16(&As[nxt][r0i][c4i],  A + (size_t)gcl0 * lda + k0 + c4i);
            cp16(&As[nxt][r1i][c4i2], A + (size_t)gcl1 * lda + k0 + c4i2);
            cp16(&Bs[nxt][r0i][c4i],  B + (size_t)(bn + r0i) * ldb + k0 + c4i);
            cp16(&Bs[nxt][r1i][c4i2], B + (size_t)(bn + r1i) * ldb + k0 + c4i2);
            asm volatile("cp.async.commit_group;");
        }

#pragma unroll
        for (int ks = 0; ks < 2; ks++) {
            const int kb = ks * 8;
            uint32_t af[4][4], bf[4][2];
#pragma unroll
            for (int mt = 0; mt < 4; mt++) {
                const int r = wm + mt * 16;
                af[mt][0] = __float_as_uint(As[cur][r + g][kb + t4]);
                af[mt][1] = __float_as_uint(As[cur][r + g + 8][kb + t4]);
                af[mt][2] = __float_as_uint(As[cur][r + g][kb + t4 + 4]);
                af[mt][3] = __float_as_uint(As[cur][r + g + 8][kb + t4 + 4]);
            }
#pragma unroll
            for (int nt = 0; nt < 4; nt++) {
                bf[nt][0] = __float_as_uint(Bs[cur][wn + nt * 8 + g][kb + t4]);
                bf[nt][1] = __float_as_uint(Bs[cur][wn + nt * 8 + g][kb + t4 + 4]);
            }
#pragma unroll
            for (int mt = 0; mt < 4; mt++)
#pragma unroll
                for (int nt = 0; nt < 4; nt++)
                    mma_tf32(acc[mt][nt], af[mt], bf[nt]);
        }
        __syncthreads();
    }

    // epilogue
#pragma unroll
    for (int mt = 0; mt < 4; mt++) {
        const int rA = bm + wm + mt * 16 + g;
        const int rB = rA + 8;
#pragma unroll
        for (int nt = 0; nt < 4; nt++) {
            const int c = bn + wn + nt * 8 + 2 * t4;
            const float b0 = bias ? bias[c] : 0.f;
            const float b1 = bias ? bias[c + 1] : 0.f;
            float v0 = acc[mt][nt][0] + b0, v1 = acc[mt][nt][1] + b1;
            float v2 = acc[mt][nt][2] + b0, v3 = acc[mt][nt][3] + b1;
            if (act == 1) {
                v0 = v0 / (1.f + __expf(-v0));
                v1 = v1 / (1.f + __expf(-v1));
                v2 = v2 / (1.f + __expf(-v2));
                v3 = v3 / (1.f + __expf(-v3));
            }
            if (rA < M) { float2 p = make_float2(v0, v1); *(float2*)&C[(size_t)rA * ldc + c] = p; }
            if (rB < M) { float2 p = make_float2(v2, v3); *(float2*)&C[(size_t)rB * ldc + c] = p; }
        }
    }
}

// ---------------------------------------------------------------------------
// Zero pad rows of g_emb (positions 0..W-2 per batch)
// ---------------------------------------------------------------------------
__global__ void zero_pad_kernel() {
    int idx = blockIdx.x * blockDim.x + threadIdx.x;
    if (idx >= BB * (WW - 1) * EE) return;
    int e = idx & (EE - 1);
    int p = (idx >> 8) % (WW - 1);
    int b = idx / ((WW - 1) * EE);
    g_emb[((size_t)b * PP + p) * EE + e] = 0.f;
}

// ---------------------------------------------------------------------------
// Layer-1 attention via tensor cores. One block (128 thr, 4 warps) per (n,h).
// Q/K/V and probabilities tf32-rounded at smem-store time; MMA loops cvt-free.
// ---------------------------------------------------------------------------
#define QS(r, c) s_q[(r) * 33 + (c)]
#define KS(r, c) s_k[(r) * 33 + (c)]
#define VS(r, c) s_v[(r) * 33 + (c)]
#define SC(r, c) s_s[(r) * 66 + (c)]

__global__ __launch_bounds__(128) void attn1_kernel(const float* __restrict__ qkv,
                                                    float* __restrict__ out) {
    __shared__ float s_q[WW * 33], s_k[WW * 33], s_v[WW * 33];
    __shared__ float s_s[WW * 66];
    const int h = blockIdx.x;
    const int n = blockIdx.y;
    const int b = n >> 10, s = n & (SS - 1);
    const int tid = threadIdx.x;
    const int lane = tid & 31, w = tid >> 5;
    const int g = lane >> 2, t4 = lane & 3;

    size_t base = ((size_t)b * PP + s) * TE + h * HD;
    for (int t = tid; t < WW * HD; t += 128) {
        int wpos = t >> 5, d = t & 31;
        size_t r = base + (size_t)wpos * TE + d;
        QS(wpos, d) = __uint_as_float(f2tf(qkv[r]));
        KS(wpos, d) = __uint_as_float(f2tf(qkv[r + EE]));
        VS(wpos, d) = __uint_as_float(f2tf(qkv[r + 2 * EE]));
    }
    __syncthreads();

    // scores: warp w -> rows 16w..16w+15, all 64 cols
    {
        float sacc[8][4];
#pragma unroll
        for (int i = 0; i < 8; i++)
#pragma unroll
            for (int j = 0; j < 4; j++) sacc[i][j] = 0.f;
#pragma unroll
        for (int k0 = 0; k0 < HD; k0 += 8) {
            uint32_t a[4];
            a[0] = __float_as_uint(QS(16 * w + g, k0 + t4));
            a[1] = __float_as_uint(QS(16 * w + g + 8, k0 + t4));
            a[2] = __float_as_uint(QS(16 * w + g, k0 + t4 + 4));
            a[3] = __float_as_uint(QS(16 * w + g + 8, k0 + t4 + 4));
#pragma unroll
            for (int nt = 0; nt < 8; nt++) {
                uint32_t bfr[2];
                bfr[0] = __float_as_uint(KS(nt * 8 + g, k0 + t4));
                bfr[1] = __float_as_uint(KS(nt * 8 + g, k0 + t4 + 4));
                mma_tf32(sacc[nt], a, bfr);
            }
        }
#pragma unroll
        for (int nt = 0; nt < 8; nt++) {
            const int r0 = 16 * w + g, c = nt * 8 + 2 * t4;
            float2 p0 = make_float2(sacc[nt][0] * ATT_SCALE, sacc[nt][1] * ATT_SCALE);
            float2 p1 = make_float2(sacc[nt][2] * ATT_SCALE, sacc[nt][3] * ATT_SCALE);
            *(float2*)&SC(r0, c) = p0;
            *(float2*)&SC(r0 + 8, c) = p1;
        }
    }
    __syncthreads();

    // softmax: 2 threads per row; write back tf32-rounded probabilities
    {
        const int row = tid >> 1, half = tid & 1;
        const int cb = half * 32;
        float mx = -1e30f;
#pragma unroll
        for (int j = 0; j < 32; j++) mx = fmaxf(mx, SC(row, cb + j));
        mx = fmaxf(mx, __shfl_xor_sync(0xffffffff, mx, 1));
        float ebuf[32];
        float sum = 0.f;
#pragma unroll
        for (int j = 0; j < 32; j++) {
            ebuf[j] = __expf(SC(row, cb + j) - mx);
            sum += ebuf[j];
        }
        sum += __shfl_xor_sync(0xffffffff, sum, 1);
        float inv = 1.f / sum;
#pragma unroll
        for (int j = 0; j < 32; j++)
            SC(row, cb + j) = __uint_as_float(f2tf(ebuf[j] * inv));
    }
    __syncthreads();

    // O = P V: m=64 (warp rows 16w..), n=32 (head dim), k=64
    {
        float oacc[4][4];
#pragma unroll
        for (int i = 0; i < 4; i++)
#pragma unroll
            for (int j = 0; j < 4; j++) oacc[i][j] = 0.f;
#pragma unroll
        for (int k0 = 0; k0 < WW; k0 += 8) {
            uint32_t a[4];
            a[0] = __float_as_uint(SC(16 * w + g, k0 + t4));
            a[1] = __float_as_uint(SC(16 * w + g + 8, k0 + t4));
            a[2] = __float_as_uint(SC(16 * w + g, k0 + t4 + 4));
            a[3] = __float_as_uint(SC(16 * w + g + 8, k0 + t4 + 4));
#pragma unroll
            for (int nt = 0; nt < 4; nt++) {
                uint32_t bfr[2];
                bfr[0] = __float_as_uint(VS(k0 + t4, nt * 8 + g));
                bfr[1] = __float_as_uint(VS(k0 + t4 + 4, nt * 8 + g));
                mma_tf32(oacc[nt], a, bfr);
            }
        }
        const size_t row0 = ((size_t)n * WW + 16 * w + g) * EE + h * HD;
        const size_t row1 = row0 + 8 * EE;
#pragma unroll
        for (int nt = 0; nt < 4; nt++) {
            const int c = nt * 8 + 2 * t4;
            *(float2*)&out[row0 + c] = make_float2(oacc[nt][0], oacc[nt][1]);
            *(float2*)&out[row1 + c] = make_float2(oacc[nt][2], oacc[nt][3]);
        }
    }
}

// ---------------------------------------------------------------------------
// Layer-2 attention (pruned): Q from compact [2048,256], KV from [NROW,512].
// ---------------------------------------------------------------------------
__global__ __launch_bounds__(64) void attn2_kernel(const float* __restrict__ q2,
                                                   const float* __restrict__ kv,
                                                   float* __restrict__ out) {
    int h = blockIdx.x;
    int n = blockIdx.y;
    int tid = threadIdx.x;
    __shared__ float ks[WW][HD + 1], vs[WW][HD + 1];
    __shared__ float q[HD], p[WW];

    size_t base = (size_t)n * WW * 512 + h * HD;
    for (int t = tid; t < WW * HD; t += 64) {
        int wpos = t >> 5, d = t & 31;
        size_t r = base + (size_t)wpos * 512 + d;
        ks[wpos][d] = kv[r];
        vs[wpos][d] = kv[r + 256];
    }
    if (tid < HD) q[tid] = q2[(size_t)n * EE + h * HD + tid];
    __syncthreads();

    {
        float dsum = 0.f;
#pragma unroll
        for (int d = 0; d < HD; d++) dsum = fmaf(q[d], ks[tid][d], dsum);
        p[tid] = dsum * ATT_SCALE;
    }
    __syncthreads();
    if (tid < 32) {
        float v = fmaxf(p[tid], p[tid + 32]);
#pragma unroll
        for (int o = 16; o > 0; o >>= 1) v = fmaxf(v, __shfl_xor_sync(0xffffffff, v, o));
        float e0 = __expf(p[tid] - v), e1 = __expf(p[tid + 32] - v);
        float sm = e0 + e1;
#pragma unroll
        for (int o = 16; o > 0; o >>= 1) sm += __shfl_xor_sync(0xffffffff, sm, o);
        float inv = 1.f / sm;
        p[tid] = e0 * inv; p[tid + 32] = e1 * inv;
    }
    __syncthreads();
    if (tid < HD) {
        float acc = 0.f;
#pragma unroll
        for (int j = 0; j < WW; j++) acc = fmaf(p[j], vs[j][tid], acc);
        out[(size_t)n * EE + h * HD + tid] = acc;
    }
}

// ---------------------------------------------------------------------------
// Fused residual-add + LayerNorm (E = 256, 256 threads/row, shuffle reduce).
// mode 0: res row = row; mode 1: res = window view of g_emb.
// ---------------------------------------------------------------------------
__global__ __launch_bounds__(256) void add_ln_kernel(
    const float* __restrict__ a, const float* __restrict__ res,
    const float* __restrict__ gamma, const float* __restrict__ beta,
    float* __restrict__ out, int mode) {
    int row = blockIdx.x;
    int e = threadIdx.x;
    int lane = e & 31, w = e >> 5;
    __shared__ float ws[8];

    size_t roff;
    if (mode == 0) roff = (size_t)row * EE;
    else {
        int n = row >> 6, wp = row & 63;
        int b = n >> 10, s = n & (SS - 1);
        roff = ((size_t)b * PP + s + wp) * EE;
    }

    float x = a[(size_t)row * EE + e] + res[roff + e];

    float s1 = x;
#pragma unroll
    for (int o = 16; o > 0; o >>= 1) s1 += __shfl_xor_sync(0xffffffff, s1, o);
    if (lane == 0) ws[w] = s1;
    __syncthreads();
    float tot = 0.f;
#pragma unroll
    for (int i = 0; i < 8; i++) tot += ws[i];
    float mean = tot * (1.f / EE);
    __syncthreads();

    float d = x - mean;
    float s2 = d * d;
#pragma unroll
    for (int o = 16; o > 0; o >>= 1) s2 += __shfl_xor_sync(0xffffffff, s2, o);
    if (lane == 0) ws[w] = s2;
    __syncthreads();
    float tot2 = 0.f;
#pragma unroll
    for (int i = 0; i < 8; i++) tot2 += ws[i];
    float var = tot2 * (1.f / EE);
    out[(size_t)row * EE + e] = d * rsqrtf(var + LN_EPS) * gamma[e] + beta[e];
}

// ---------------------------------------------------------------------------
// Gather last window rows: x2[(n*64+63)] -> xlast[n]
// ---------------------------------------------------------------------------
__global__ void gather_last_kernel(const float* __restrict__ x2,
                                   float* __restrict__ xlast) {
    int idx = blockIdx.x * blockDim.x + threadIdx.x;
    if (idx >= NWIN * EE) return;
    int n = idx >> 8, e = idx & 255;
    xlast[idx] = x2[((size_t)n * WW + (WW - 1)) * EE + e];
}

// ---------------------------------------------------------------------------
// Head: out[n,o] = y[n] . head_w[o] + head_b[o]
// ---------------------------------------------------------------------------
__global__ void head_kernel(const float* __restrict__ y,
                            const float* __restrict__ hw,
                            const float* __restrict__ hb,
                            float* __restrict__ out) {
    int idx = blockIdx.x * blockDim.x + threadIdx.x;
    if (idx >= NWIN * OUTD) return;
    int n = idx / OUTD, o = idx % OUTD;
    const float* yr = y + (size_t)n * EE;
    const float* wr = hw + (size_t)o * EE;
    float acc = hb[o];
#pragma unroll 8
    for (int k = 0; k < EE; k++) acc = fmaf(yr[k], wr[k], acc);
    out[idx] = acc;
}

// ---------------------------------------------------------------------------
// Host launch
// ---------------------------------------------------------------------------
static inline dim3 tgrid(int M, int N) {
    return dim3(N / 128, (M + 127) / 128);
}

extern "C" void kernel_launch(void* const* d_in, const int* in_sizes, int n_in,
                              void* d_out, int out_size) {
    const float* inputs     = (const float*)d_in[0];
    const float* embed_w    = (const float*)d_in[1];
    const float* embed_b    = (const float*)d_in[2];
    const float* qkv_w      = (const float*)d_in[3];
    const float* qkv_b      = (const float*)d_in[4];
    const float* attn_out_w = (const float*)d_in[5];
    const float* attn_out_b = (const float*)d_in[6];
    const float* ln1_g      = (const float*)d_in[7];
    const float* ln1_b      = (const float*)d_in[8];
    const float* ffn1_w     = (const float*)d_in[9];
    const float* ffn1_b     = (const float*)d_in[10];
    const float* ffn2_w     = (const float*)d_in[11];
    const float* ffn2_b     = (const float*)d_in[12];
    const float* ln2_g      = (const float*)d_in[13];
    const float* ln2_b      = (const float*)d_in[14];
    const float* head_w     = (const float*)d_in[15];
    const float* head_b     = (const float*)d_in[16];
    float* out = (float*)d_out;

    float *emb, *qkv, *bufA, *bufB, *bufC, *xlast, *r1, *r2, *r3;
    cudaGetSymbolAddress((void**)&emb,   g_emb);
    cudaGetSymbolAddress((void**)&qkv,   g_qkv);
    cudaGetSymbolAddress((void**)&bufA,  g_bufA);
    cudaGetSymbolAddress((void**)&bufB,  g_bufB);
    cudaGetSymbolAddress((void**)&bufC,  g_bufC);
    cudaGetSymbolAddress((void**)&xlast, g_xlast);
    cudaGetSymbolAddress((void**)&r1,    g_r1);
    cudaGetSymbolAddress((void**)&r2,    g_r2);
    cudaGetSymbolAddress((void**)&r3,    g_r3);

    // 1. zero pad rows, then embedding GEMMs (one per batch, M=1024)
    zero_pad_kernel<<<(BB * (WW - 1) * EE + 255) / 256, 256>>>();
    for (int b = 0; b < BB; b++) {
        tgemm<<<tgrid(SS, EE), 256>>>(inputs + (size_t)b * SS * FIN, embed_w, embed_b,
                                      emb + ((size_t)b * PP + (WW - 1)) * EE,
                                      SS, EE, FIN, FIN, FIN, EE, 0);
    }
    // 2. Layer-1 QKV (shared): [2174,256] x [768,256]^T
    tgemm<<<tgrid(BB * PP, TE), 256>>>(emb, qkv_w, qkv_b, qkv,
                                       BB * PP, TE, EE, EE, EE, TE, 0);
    // 3. attention -> bufA [131072,256]
    attn1_kernel<<<dim3(NH, NWIN), 128>>>(qkv, bufA);
    // 4. attn-out proj -> bufB
    tgemm<<<tgrid(NROW, EE), 256>>>(bufA, attn_out_w, attn_out_b, bufB,
                                    NROW, EE, EE, EE, EE, EE, 0);
    // 5. x1 = LN1(emb_window + bufB) -> bufA
    add_ln_kernel<<<NROW, 256>>>(bufB, emb, ln1_g, ln1_b, bufA, 1);
    // 6. FFN hidden (silu) -> bufC [131072,1024]
    tgemm<<<tgrid(NROW, FF), 256>>>(bufA, ffn1_w, ffn1_b, bufC,
                                    NROW, FF, EE, EE, EE, FF, 1);
    // 7. FFN out -> bufB
    tgemm<<<tgrid(NROW, EE), 256>>>(bufC, ffn2_w, ffn2_b, bufB,
                                    NROW, EE, FF, FF, FF, EE, 0);
    // 8. x2 = LN2(x1 + bufB) -> bufA
    add_ln_kernel<<<NROW, 256>>>(bufB, bufA, ln2_g, ln2_b, bufA, 0);

    // ---- Layer 2 (output pruned) ----
    // 9. gather last rows -> xlast; Q only for last rows -> r2
    gather_last_kernel<<<(NWIN * EE + 255) / 256, 256>>>(bufA, xlast);
    tgemm<<<tgrid(NWIN, EE), 256>>>(xlast, qkv_w + (size_t)TE * EE, qkv_b + TE,
                                    r2, NWIN, EE, EE, EE, EE, EE, 0);
    // 10. KV for all rows -> bufC [131072,512]
    tgemm<<<tgrid(NROW, 512), 256>>>(bufA, qkv_w + (size_t)TE * EE + (size_t)EE * EE,
                                     qkv_b + TE + EE, bufC,
                                     NROW, 512, EE, EE, EE, 512, 0);
    // 11. attention (q last row) -> r1
    attn2_kernel<<<dim3(NH, NWIN), 64>>>(r2, bufC, r1);
    // 12. proj -> r2
    tgemm<<<tgrid(NWIN, EE), 256>>>(r1, attn_out_w + (size_t)EE * EE, attn_out_b + EE,
                                    r2, NWIN, EE, EE, EE, EE, EE, 0);
    // 13. y = LN1_l2(xlast + r2) -> r1
    add_ln_kernel<<<NWIN, 256>>>(r2, xlast, ln1_g + EE, ln1_b + EE, r1, 0);
    // 14. h2 = silu(y @ W1^T) -> r3
    tgemm<<<tgrid(NWIN, FF), 256>>>(r1, ffn1_w + (size_t)FF * EE, ffn1_b + FF,
                                    r3, NWIN, FF, EE, EE, EE, FF, 1);
    // 15. f2 -> r2
    tgemm<<<tgrid(NWIN, EE), 256>>>(r3, ffn2_w + (size_t)EE * FF, ffn2_b + EE,
                                    r2, NWIN, EE, FF, FF, FF, EE, 0);
    // 16. y2 = LN2_l2(y + f2) -> r1
    add_ln_kernel<<<NWIN, 256>>>(r2, r1, ln2_g + EE, ln2_b + EE, r1, 0);
    // 17. head -> d_out
    head_kernel<<<(NWIN * OUTD + 255) / 256, 256>>>(r1, head_w, head_b, out);
}

// round 9
// speedup vs baseline: 1.0440x; 1.0440x over previous
#include <cuda_runtime.h>
#include <cuda_bf16.h>
#include <math.h>
#include <stdint.h>

// ---------------------------------------------------------------------------
// Problem constants
// ---------------------------------------------------------------------------
#define BB 2
#define SS 1024
#define WW 64
#define PP (SS + WW - 1)   // 1087
#define EE 256
#define FIN 64
#define FF 1024
#define TE 768
#define NH 8
#define HD 32
#define NWIN (BB * SS)     // 2048
#define NROW (NWIN * WW)   // 131072
#define OUTD 10
#define LN_EPS 1e-5f
#define ATT_SCALE 0.17677669529663687f

// ---------------------------------------------------------------------------
// Scratch
// ---------------------------------------------------------------------------
__device__ float g_emb  [BB * PP * EE];
__device__ float g_qkv  [BB * PP * TE];
__device__ float g_bufA [(size_t)NROW * EE];
__device__ float g_bufB [(size_t)NROW * EE];
__device__ float g_bufC [(size_t)NROW * FF];   // FFN hidden; later KV2 (stride 512)
__device__ float g_xlast[NWIN * EE];
__device__ float g_r1   [NWIN * EE];
__device__ float g_r2   [NWIN * EE];
__device__ float g_r3   [NWIN * FF];

// ---------------------------------------------------------------------------
// Common MMA helpers
// ---------------------------------------------------------------------------
__device__ __forceinline__ uint32_t f2tf(float f) {
    uint32_t r;
    asm("cvt.rna.tf32.f32 %0, %1;" : "=r"(r) : "f"(f));
    return r;
}

__device__ __forceinline__ void mma_tf32(float* c, const uint32_t* a, const uint32_t* b) {
    asm volatile(
        "mma.sync.aligned.m16n8k8.row.col.f32.tf32.tf32.f32 "
        "{%0,%1,%2,%3},{%4,%5,%6,%7},{%8,%9},{%0,%1,%2,%3};"
        : "+f"(c[0]), "+f"(c[1]), "+f"(c[2]), "+f"(c[3])
        : "r"(a[0]), "r"(a[1]), "r"(a[2]), "r"(a[3]), "r"(b[0]), "r"(b[1]));
}

__device__ __forceinline__ void cp16(void* s, const void* g) {
    uint32_t sa = (uint32_t)__cvta_generic_to_shared(s);
    asm volatile("cp.async.cg.shared.global [%0], [%1], 16;" :: "r"(sa), "l"(g));
}

// in-place tf32-round 4 consecutive floats in smem
__device__ __forceinline__ void cvt4(float* p) {
    float4 v = *(float4*)p;
    uint4 u;
    u.x = f2tf(v.x); u.y = f2tf(v.y); u.z = f2tf(v.z); u.w = f2tf(v.w);
    *(uint4*)p = u;
}

// ---------------------------------------------------------------------------
// TF32 tensor-core GEMM (NT): C[m,n] = act(sum_k A[m,k]*B[n,k] + bias[n])
// 128x128 tile, BK=16, 2-stage cp.async, ONE barrier per k-tile.
// Loop order per tile t: wait own-tile cp.async -> cvt own 16 floats in smem
// -> barrier -> prefetch tile t+1 (other buffer; safe: all warps done reading
// it) -> cvt-free MMA phase overlapping the prefetch.
// Requires: K % 16 == 0, N % 128 == 0. act: 0 none, 1 silu.
// ---------------------------------------------------------------------------
#define TBK 16
#define SMS 20   // smem row stride (16 + 4 pad)

__global__ __launch_bounds__(256, 2) void tgemm(
    const float* __restrict__ A, const float* __restrict__ B,
    const float* __restrict__ bias, float* __restrict__ C,
    int M, int N, int K, int lda, int ldb, int ldc, int act) {
    __shared__ __align__(16) float As[2][128][SMS];
    __shared__ __align__(16) float Bs[2][128][SMS];
    const int tid = threadIdx.x;
    const int bm = blockIdx.y * 128, bn = blockIdx.x * 128;
    const int lane = tid & 31, wid = tid >> 5;
    const int wm = (wid >> 2) * 64, wn = (wid & 3) * 32;
    const int g = lane >> 2, t4 = lane & 3;

    float acc[4][4][4];
#pragma unroll
    for (int i = 0; i < 4; i++)
#pragma unroll
        for (int j = 0; j < 4; j++)
#pragma unroll
            for (int k = 0; k < 4; k++) acc[i][j][k] = 0.f;

    const int T = K / TBK;
    const int r0i = tid >> 2, c4i = (tid & 3) << 2;
    const int r1i = (tid + 256) >> 2, c4i2 = ((tid + 256) & 3) << 2;
    int gcl0 = bm + r0i; if (gcl0 >= M) gcl0 = M - 1;
    int gcl1 = bm + r1i; if (gcl1 >= M) gcl1 = M - 1;

    // prologue: tile 0
    cp16(&As[0][r0i][c4i],  A + (size_t)gcl0 * lda + c4i);
    cp16(&As[0][r1i][c4i2], A + (size_t)gcl1 * lda + c4i2);
    cp16(&Bs[0][r0i][c4i],  B + (size_t)(bn + r0i) * ldb + c4i);
    cp16(&Bs[0][r1i][c4i2], B + (size_t)(bn + r1i) * ldb + c4i2);
    asm volatile("cp.async.commit_group;");

    for (int t = 0; t < T; t++) {
        const int cur = t & 1;
        // only this tile's group is outstanding (prefetch happens post-barrier)
        asm volatile("cp.async.wait_group 0;");
        // convert the 16 floats THIS thread copied (its own group -> visible)
        cvt4(&As[cur][r0i][c4i]);
        cvt4(&As[cur][r1i][c4i2]);
        cvt4(&Bs[cur][r0i][c4i]);
        cvt4(&Bs[cur][r1i][c4i2]);
        __syncthreads();   // cvt done everywhere; prev-tile readers all passed

        if (t + 1 < T) {
            const int k0 = (t + 1) * TBK;
            const int nxt = cur ^ 1;
            cp16(&As[nxt][r0i][c4i],  A + (size_t)gcl0 * lda + k0 + c4i);
            cp16(&As[nxt][r1i][c4i2], A + (size_t)gcl1 * lda + k0 + c4i2);
            cp16(&Bs[nxt][r0i][c4i],  B + (size_t)(bn + r0i) * ldb + k0 + c4i);
            cp16(&Bs[nxt][r1i][c4i2], B + (size_t)(bn + r1i) * ldb + k0 + c4i2);
            asm volatile("cp.async.commit_group;");
        }

        // cvt-free MMA phase, overlapping the in-flight prefetch
#pragma unroll
        for (int ks = 0; ks < 2; ks++) {
            const int kb = ks * 8;
            uint32_t af[4][4], bf[4][2];
#pragma unroll
            for (int mt = 0; mt < 4; mt++) {
                const int r = wm + mt * 16;
                af[mt][0] = __float_as_uint(As[cur][r + g][kb + t4]);
                af[mt][1] = __float_as_uint(As[cur][r + g + 8][kb + t4]);
                af[mt][2] = __float_as_uint(As[cur][r + g][kb + t4 + 4]);
                af[mt][3] = __float_as_uint(As[cur][r + g + 8][kb + t4 + 4]);
            }
#pragma unroll
            for (int nt = 0; nt < 4; nt++) {
                bf[nt][0] = __float_as_uint(Bs[cur][wn + nt * 8 + g][kb + t4]);
                bf[nt][1] = __float_as_uint(Bs[cur][wn + nt * 8 + g][kb + t4 + 4]);
            }
#pragma unroll
            for (int mt = 0; mt < 4; mt++)
#pragma unroll
                for (int nt = 0; nt < 4; nt++)
                    mma_tf32(acc[mt][nt], af[mt], bf[nt]);
        }
        // no barrier here: next iteration's cvt touches the OTHER buffer, and
        // its pre-prefetch barrier protects this buffer before overwrite.
    }

    // epilogue
#pragma unroll
    for (int mt = 0; mt < 4; mt++) {
        const int rA = bm + wm + mt * 16 + g;
        const int rB = rA + 8;
#pragma unroll
        for (int nt = 0; nt < 4; nt++) {
            const int c = bn + wn + nt * 8 + 2 * t4;
            const float b0 = bias ? bias[c] : 0.f;
            const float b1 = bias ? bias[c + 1] : 0.f;
            float v0 = acc[mt][nt][0] + b0, v1 = acc[mt][nt][1] + b1;
            float v2 = acc[mt][nt][2] + b0, v3 = acc[mt][nt][3] + b1;
            if (act == 1) {
                v0 = v0 / (1.f + __expf(-v0));
                v1 = v1 / (1.f + __expf(-v1));
                v2 = v2 / (1.f + __expf(-v2));
                v3 = v3 / (1.f + __expf(-v3));
            }
            if (rA < M) { float2 p = make_float2(v0, v1); *(float2*)&C[(size_t)rA * ldc + c] = p; }
            if (rB < M) { float2 p = make_float2(v2, v3); *(float2*)&C[(size_t)rB * ldc + c] = p; }
        }
    }
}

// ---------------------------------------------------------------------------
// Zero pad rows of g_emb (positions 0..W-2 per batch)
// ---------------------------------------------------------------------------
__global__ void zero_pad_kernel() {
    int idx = blockIdx.x * blockDim.x + threadIdx.x;
    if (idx >= BB * (WW - 1) * EE) return;
    int e = idx & (EE - 1);
    int p = (idx >> 8) % (WW - 1);
    int b = idx / ((WW - 1) * EE);
    g_emb[((size_t)b * PP + p) * EE + e] = 0.f;
}

// ---------------------------------------------------------------------------
// Layer-1 attention via tensor cores. One block (128 thr, 4 warps) per (n,h).
// Q/K/V and probabilities tf32-rounded at smem-store time; MMA loops cvt-free.
// ---------------------------------------------------------------------------
#define QS(r, c) s_q[(r) * 33 + (c)]
#define KS(r, c) s_k[(r) * 33 + (c)]
#define VS(r, c) s_v[(r) * 33 + (c)]
#define SC(r, c) s_s[(r) * 66 + (c)]

__global__ __launch_bounds__(128) void attn1_kernel(const float* __restrict__ qkv,
                                                    float* __restrict__ out) {
    __shared__ float s_q[WW * 33], s_k[WW * 33], s_v[WW * 33];
    __shared__ float s_s[WW * 66];
    const int h = blockIdx.x;
    const int n = blockIdx.y;
    const int b = n >> 10, s = n & (SS - 1);
    const int tid = threadIdx.x;
    const int lane = tid & 31, w = tid >> 5;
    const int g = lane >> 2, t4 = lane & 3;

    size_t base = ((size_t)b * PP + s) * TE + h * HD;
    for (int t = tid; t < WW * HD; t += 128) {
        int wpos = t >> 5, d = t & 31;
        size_t r = base + (size_t)wpos * TE + d;
        QS(wpos, d) = __uint_as_float(f2tf(qkv[r]));
        KS(wpos, d) = __uint_as_float(f2tf(qkv[r + EE]));
        VS(wpos, d) = __uint_as_float(f2tf(qkv[r + 2 * EE]));
    }
    __syncthreads();

    // scores: warp w -> rows 16w..16w+15, all 64 cols
    {
        float sacc[8][4];
#pragma unroll
        for (int i = 0; i < 8; i++)
#pragma unroll
            for (int j = 0; j < 4; j++) sacc[i][j] = 0.f;
#pragma unroll
        for (int k0 = 0; k0 < HD; k0 += 8) {
            uint32_t a[4];
            a[0] = __float_as_uint(QS(16 * w + g, k0 + t4));
            a[1] = __float_as_uint(QS(16 * w + g + 8, k0 + t4));
            a[2] = __float_as_uint(QS(16 * w + g, k0 + t4 + 4));
            a[3] = __float_as_uint(QS(16 * w + g + 8, k0 + t4 + 4));
#pragma unroll
            for (int nt = 0; nt < 8; nt++) {
                uint32_t bfr[2];
                bfr[0] = __float_as_uint(KS(nt * 8 + g, k0 + t4));
                bfr[1] = __float_as_uint(KS(nt * 8 + g, k0 + t4 + 4));
                mma_tf32(sacc[nt], a, bfr);
            }
        }
#pragma unroll
        for (int nt = 0; nt < 8; nt++) {
            const int r0 = 16 * w + g, c = nt * 8 + 2 * t4;
            float2 p0 = make_float2(sacc[nt][0] * ATT_SCALE, sacc[nt][1] * ATT_SCALE);
            float2 p1 = make_float2(sacc[nt][2] * ATT_SCALE, sacc[nt][3] * ATT_SCALE);
            *(float2*)&SC(r0, c) = p0;
            *(float2*)&SC(r0 + 8, c) = p1;
        }
    }
    __syncthreads();

    // softmax: 2 threads per row; write back tf32-rounded probabilities
    {
        const int row = tid >> 1, half = tid & 1;
        const int cb = half * 32;
        float mx = -1e30f;
#pragma unroll
        for (int j = 0; j < 32; j++) mx = fmaxf(mx, SC(row, cb + j));
        mx = fmaxf(mx, __shfl_xor_sync(0xffffffff, mx, 1));
        float ebuf[32];
        float sum = 0.f;
#pragma unroll
        for (int j = 0; j < 32; j++) {
            ebuf[j] = __expf(SC(row, cb + j) - mx);
            sum += ebuf[j];
        }
        sum += __shfl_xor_sync(0xffffffff, sum, 1);
        float inv = 1.f / sum;
#pragma unroll
        for (int j = 0; j < 32; j++)
            SC(row, cb + j) = __uint_as_float(f2tf(ebuf[j] * inv));
    }
    __syncthreads();

    // O = P V: m=64 (warp rows 16w..), n=32 (head dim), k=64
    {
        float oacc[4][4];
#pragma unroll
        for (int i = 0; i < 4; i++)
#pragma unroll
            for (int j = 0; j < 4; j++) oacc[i][j] = 0.f;
#pragma unroll
        for (int k0 = 0; k0 < WW; k0 += 8) {
            uint32_t a[4];
            a[0] = __float_as_uint(SC(16 * w + g, k0 + t4));
            a[1] = __float_as_uint(SC(16 * w + g + 8, k0 + t4));
            a[2] = __float_as_uint(SC(16 * w + g, k0 + t4 + 4));
            a[3] = __float_as_uint(SC(16 * w + g + 8, k0 + t4 + 4));
#pragma unroll
            for (int nt = 0; nt < 4; nt++) {
                uint32_t bfr[2];
                bfr[0] = __float_as_uint(VS(k0 + t4, nt * 8 + g));
                bfr[1] = __float_as_uint(VS(k0 + t4 + 4, nt * 8 + g));
                mma_tf32(oacc[nt], a, bfr);
            }
        }
        const size_t row0 = ((size_t)n * WW + 16 * w + g) * EE + h * HD;
        const size_t row1 = row0 + 8 * EE;
#pragma unroll
        for (int nt = 0; nt < 4; nt++) {
            const int c = nt * 8 + 2 * t4;
            *(float2*)&out[row0 + c] = make_float2(oacc[nt][0], oacc[nt][1]);
            *(float2*)&out[row1 + c] = make_float2(oacc[nt][2], oacc[nt][3]);
        }
    }
}

// ---------------------------------------------------------------------------
// Layer-2 attention (pruned): Q from compact [2048,256], KV from [NROW,512].
// ---------------------------------------------------------------------------
__global__ __launch_bounds__(64) void attn2_kernel(const float* __restrict__ q2,
                                                   const float* __restrict__ kv,
                                                   float* __restrict__ out) {
    int h = blockIdx.x;
    int n = blockIdx.y;
    int tid = threadIdx.x;
    __shared__ float ks[WW][HD + 1], vs[WW][HD + 1];
    __shared__ float q[HD], p[WW];

    size_t base = (size_t)n * WW * 512 + h * HD;
    for (int t = tid; t < WW * HD; t += 64) {
        int wpos = t >> 5, d = t & 31;
        size_t r = base + (size_t)wpos * 512 + d;
        ks[wpos][d] = kv[r];
        vs[wpos][d] = kv[r + 256];
    }
    if (tid < HD) q[tid] = q2[(size_t)n * EE + h * HD + tid];
    __syncthreads();

    {
        float dsum = 0.f;
#pragma unroll
        for (int d = 0; d < HD; d++) dsum = fmaf(q[d], ks[tid][d], dsum);
        p[tid] = dsum * ATT_SCALE;
    }
    __syncthreads();
    if (tid < 32) {
        float v = fmaxf(p[tid], p[tid + 32]);
#pragma unroll
        for (int o = 16; o > 0; o >>= 1) v = fmaxf(v, __shfl_xor_sync(0xffffffff, v, o));
        float e0 = __expf(p[tid] - v), e1 = __expf(p[tid + 32] - v);
        float sm = e0 + e1;
#pragma unroll
        for (int o = 16; o > 0; o >>= 1) sm += __shfl_xor_sync(0xffffffff, sm, o);
        float inv = 1.f / sm;
        p[tid] = e0 * inv; p[tid + 32] = e1 * inv;
    }
    __syncthreads();
    if (tid < HD) {
        float acc = 0.f;
#pragma unroll
        for (int j = 0; j < WW; j++) acc = fmaf(p[j], vs[j][tid], acc);
        out[(size_t)n * EE + h * HD + tid] = acc;
    }
}

// ---------------------------------------------------------------------------
// Fused residual-add + LayerNorm (E = 256, 256 threads/row, shuffle reduce).
// mode 0: res row = row; mode 1: res = window view of g_emb.
// ---------------------------------------------------------------------------
__global__ __launch_bounds__(256) void add_ln_kernel(
    const float* __restrict__ a, const float* __restrict__ res,
    const float* __restrict__ gamma, const float* __restrict__ beta,
    float* __restrict__ out, int mode) {
    int row = blockIdx.x;
    int e = threadIdx.x;
    int lane = e & 31, w = e >> 5;
    __shared__ float ws[8];

    size_t roff;
    if (mode == 0) roff = (size_t)row * EE;
    else {
        int n = row >> 6, wp = row & 63;
        int b = n >> 10, s = n & (SS - 1);
        roff = ((size_t)b * PP + s + wp) * EE;
    }

    float x = a[(size_t)row * EE + e] + res[roff + e];

    float s1 = x;
#pragma unroll
    for (int o = 16; o > 0; o >>= 1) s1 += __shfl_xor_sync(0xffffffff, s1, o);
    if (lane == 0) ws[w] = s1;
    __syncthreads();
    float tot = 0.f;
#pragma unroll
    for (int i = 0; i < 8; i++) tot += ws[i];
    float mean = tot * (1.f / EE);
    __syncthreads();

    float d = x - mean;
    float s2 = d * d;
#pragma unroll
    for (int o = 16; o > 0; o >>= 1) s2 += __shfl_xor_sync(0xffffffff, s2, o);
    if (lane == 0) ws[w] = s2;
    __syncthreads();
    float tot2 = 0.f;
#pragma unroll
    for (int i = 0; i < 8; i++) tot2 += ws[i];
    float var = tot2 * (1.f / EE);
    out[(size_t)row * EE + e] = d * rsqrtf(var + LN_EPS) * gamma[e] + beta[e];
}

// ---------------------------------------------------------------------------
// Gather last window rows: x2[(n*64+63)] -> xlast[n]
// ---------------------------------------------------------------------------
__global__ void gather_last_kernel(const float* __restrict__ x2,
                                   float* __restrict__ xlast) {
    int idx = blockIdx.x * blockDim.x + threadIdx.x;
    if (idx >= NWIN * EE) return;
    int n = idx >> 8, e = idx & 255;
    xlast[idx] = x2[((size_t)n * WW + (WW - 1)) * EE + e];
}

// ---------------------------------------------------------------------------
// Head: out[n,o] = y[n] . head_w[o] + head_b[o]
// ---------------------------------------------------------------------------
__global__ void head_kernel(const float* __restrict__ y,
                            const float* __restrict__ hw,
                            const float* __restrict__ hb,
                            float* __restrict__ out) {
    int idx = blockIdx.x * blockDim.x + threadIdx.x;
    if (idx >= NWIN * OUTD) return;
    int n = idx / OUTD, o = idx % OUTD;
    const float* yr = y + (size_t)n * EE;
    const float* wr = hw + (size_t)o * EE;
    float acc = hb[o];
#pragma unroll 8
    for (int k = 0; k < EE; k++) acc = fmaf(yr[k], wr[k], acc);
    out[idx] = acc;
}

// ---------------------------------------------------------------------------
// Host launch
// ---------------------------------------------------------------------------
static inline dim3 tgrid(int M, int N) {
    return dim3(N / 128, (M + 127) / 128);
}

extern "C" void kernel_launch(void* const* d_in, const int* in_sizes, int n_in,
                              void* d_out, int out_size) {
    const float* inputs     = (const float*)d_in[0];
    const float* embed_w    = (const float*)d_in[1];
    const float* embed_b    = (const float*)d_in[2];
    const float* qkv_w      = (const float*)d_in[3];
    const float* qkv_b      = (const float*)d_in[4];
    const float* attn_out_w = (const float*)d_in[5];
    const float* attn_out_b = (const float*)d_in[6];
    const float* ln1_g      = (const float*)d_in[7];
    const float* ln1_b      = (const float*)d_in[8];
    const float* ffn1_w     = (const float*)d_in[9];
    const float* ffn1_b     = (const float*)d_in[10];
    const float* ffn2_w     = (const float*)d_in[11];
    const float* ffn2_b     = (const float*)d_in[12];
    const float* ln2_g      = (const float*)d_in[13];
    const float* ln2_b      = (const float*)d_in[14];
    const float* head_w     = (const float*)d_in[15];
    const float* head_b     = (const float*)d_in[16];
    float* out = (float*)d_out;

    float *emb, *qkv, *bufA, *bufB, *bufC, *xlast, *r1, *r2, *r3;
    cudaGetSymbolAddress((void**)&emb,   g_emb);
    cudaGetSymbolAddress((void**)&qkv,   g_qkv);
    cudaGetSymbolAddress((void**)&bufA,  g_bufA);
    cudaGetSymbolAddress((void**)&bufB,  g_bufB);
    cudaGetSymbolAddress((void**)&bufC,  g_bufC);
    cudaGetSymbolAddress((void**)&xlast, g_xlast);
    cudaGetSymbolAddress((void**)&r1,    g_r1);
    cudaGetSymbolAddress((void**)&r2,    g_r2);
    cudaGetSymbolAddress((void**)&r3,    g_r3);

    // 1. zero pad rows, then embedding GEMMs (one per batch, M=1024)
    zero_pad_kernel<<<(BB * (WW - 1) * EE + 255) / 256, 256>>>();
    for (int b = 0; b < BB; b++) {
        tgemm<<<tgrid(SS, EE), 256>>>(inputs + (size_t)b * SS * FIN, embed_w, embed_b,
                                      emb + ((size_t)b * PP + (WW - 1)) * EE,
                                      SS, EE, FIN, FIN, FIN, EE, 0);
    }
    // 2. Layer-1 QKV (shared): [2174,256] x [768,256]^T
    tgemm<<<tgrid(BB * PP, TE), 256>>>(emb, qkv_w, qkv_b, qkv,
                                       BB * PP, TE, EE, EE, EE, TE, 0);
    // 3. attention -> bufA [131072,256]
    attn1_kernel<<<dim3(NH, NWIN), 128>>>(qkv, bufA);
    // 4. attn-out proj -> bufB
    tgemm<<<tgrid(NROW, EE), 256>>>(bufA, attn_out_w, attn_out_b, bufB,
                                    NROW, EE, EE, EE, EE, EE, 0);
    // 5. x1 = LN1(emb_window + bufB) -> bufA
    add_ln_kernel<<<NROW, 256>>>(bufB, emb, ln1_g, ln1_b, bufA, 1);
    // 6. FFN hidden (silu) -> bufC [131072,1024]
    tgemm<<<tgrid(NROW, FF), 256>>>(bufA, ffn1_w, ffn1_b, bufC,
                                    NROW, FF, EE, EE, EE, FF, 1);
    // 7. FFN out -> bufB
    tgemm<<<tgrid(NROW, EE), 256>>>(bufC, ffn2_w, ffn2_b, bufB,
                                    NROW, EE, FF, FF, FF, EE, 0);
    // 8. x2 = LN2(x1 + bufB) -> bufA
    add_ln_kernel<<<NROW, 256>>>(bufB, bufA, ln2_g, ln2_b, bufA, 0);

    // ---- Layer 2 (output pruned) ----
    // 9. gather last rows -> xlast; Q only for last rows -> r2
    gather_last_kernel<<<(NWIN * EE + 255) / 256, 256>>>(bufA, xlast);
    tgemm<<<tgrid(NWIN, EE), 256>>>(xlast, qkv_w + (size_t)TE * EE, qkv_b + TE,
                                    r2, NWIN, EE, EE, EE, EE, EE, 0);
    // 10. KV for all rows -> bufC [131072,512]
    tgemm<<<tgrid(NROW, 512), 256>>>(bufA, qkv_w + (size_t)TE * EE + (size_t)EE * EE,
                                     qkv_b + TE + EE, bufC,
                                     NROW, 512, EE, EE, EE, 512, 0);
    // 11. attention (q last row) -> r1
    attn2_kernel<<<dim3(NH, NWIN), 64>>>(r2, bufC, r1);
    // 12. proj -> r2
    tgemm<<<tgrid(NWIN, EE), 256>>>(r1, attn_out_w + (size_t)EE * EE, attn_out_b + EE,
                                    r2, NWIN, EE, EE, EE, EE, EE, 0);
    // 13. y = LN1_l2(xlast + r2) -> r1
    add_ln_kernel<<<NWIN, 256>>>(r2, xlast, ln1_g + EE, ln1_b + EE, r1, 0);
    // 14. h2 = silu(y @ W1^T) -> r3
    tgemm<<<tgrid(NWIN, FF), 256>>>(r1, ffn1_w + (size_t)FF * EE, ffn1_b + FF,
                                    r3, NWIN, FF, EE, EE, EE, FF, 1);
    // 15. f2 -> r2
    tgemm<<<tgrid(NWIN, EE), 256>>>(r3, ffn2_w + (size_t)EE * FF, ffn2_b + EE,
                                    r2, NWIN, EE, FF, FF, FF, EE, 0);
    // 16. y2 = LN2_l2(y + f2) -> r1
    add_ln_kernel<<<NWIN, 256>>>(r2, r1, ln2_g + EE, ln2_b + EE, r1, 0);
    // 17. head -> d_out
    head_kernel<<<(NWIN * OUTD + 255) / 256, 256>>>(r1, head_w, head_b, out);
}

// round 11
// speedup vs baseline: 1.6794x; 1.6085x over previous
#include <cuda_runtime.h>
#include <cuda_fp16.h>
#include <math.h>
#include <stdint.h>

// ---------------------------------------------------------------------------
// Problem constants
// ---------------------------------------------------------------------------
#define BB 2
#define SS 1024
#define WW 64
#define PP (SS + WW - 1)   // 1087
#define EE 256
#define FIN 64
#define FF 1024
#define TE 768
#define NH 8
#define HD 32
#define NWIN (BB * SS)     // 2048
#define NROW (NWIN * WW)   // 131072
#define OUTD 10
#define LN_EPS 1e-5f
#define ATT_SCALE 0.17677669529663687f

// ---------------------------------------------------------------------------
// Scratch (fp32)
// ---------------------------------------------------------------------------
__device__ float g_emb  [BB * PP * EE];
__device__ float g_qkv  [BB * PP * TE];
__device__ float g_bufA [(size_t)NROW * EE];   // x1 / x2
__device__ float g_bufB [(size_t)NROW * EE];   // GEMM fp32 outputs
__device__ float g_kv2  [(size_t)NROW * 512];  // layer-2 K,V
__device__ float g_xlast[NWIN * EE];
__device__ float g_r1   [NWIN * EE];
__device__ float g_r2   [NWIN * EE];

// Scratch (fp16) — GEMM operands
__device__ __half g_in_h  [BB * SS * FIN];
__device__ __half g_ew_h  [EE * FIN];
__device__ __half g_qw_h  [2 * TE * EE];
__device__ __half g_aw_h  [2 * EE * EE];
__device__ __half g_f1w_h [2 * FF * EE];
__device__ __half g_f2w_h [2 * EE * FF];
__device__ __half g_emb_h [BB * PP * EE];
__device__ __half g_attn_h[(size_t)NROW * EE];
__device__ __half g_x_h   [(size_t)NROW * EE];
__device__ __half g_ffh_h [(size_t)NROW * FF];
__device__ __half g_xlast_h[NWIN * EE];
__device__ __half g_r1_h  [NWIN * EE];
__device__ __half g_r3_h  [NWIN * FF];

// ---------------------------------------------------------------------------
// MMA helpers
// ---------------------------------------------------------------------------
__device__ __forceinline__ uint32_t f2tf(float f) {
    uint32_t r;
    asm("cvt.rna.tf32.f32 %0, %1;" : "=r"(r) : "f"(f));
    return r;
}

__device__ __forceinline__ void mma_tf32(float* c, const uint32_t* a, const uint32_t* b) {
    asm volatile(
        "mma.sync.aligned.m16n8k8.row.col.f32.tf32.tf32.f32 "
        "{%0,%1,%2,%3},{%4,%5,%6,%7},{%8,%9},{%0,%1,%2,%3};"
        : "+f"(c[0]), "+f"(c[1]), "+f"(c[2]), "+f"(c[3])
        : "r"(a[0]), "r"(a[1]), "r"(a[2]), "r"(a[3]), "r"(b[0]), "r"(b[1]));
}

__device__ __forceinline__ void mma_f16(float* c, const uint32_t* a, const uint32_t* b) {
    asm volatile(
        "mma.sync.aligned.m16n8k16.row.col.f32.f16.f16.f32 "
        "{%0,%1,%2,%3},{%4,%5,%6,%7},{%8,%9},{%0,%1,%2,%3};"
        : "+f"(c[0]), "+f"(c[1]), "+f"(c[2]), "+f"(c[3])
        : "r"(a[0]), "r"(a[1]), "r"(a[2]), "r"(a[3]), "r"(b[0]), "r"(b[1]));
}

__device__ __forceinline__ void cp16(void* s, const void* g) {
    uint32_t sa = (uint32_t)__cvta_generic_to_shared(s);
    asm volatile("cp.async.cg.shared.global [%0], [%1], 16;" :: "r"(sa), "l"(g));
}

// ---------------------------------------------------------------------------
// FP16 tensor-core GEMM (NT): C = act(A[M,K] * B[N,K]^T + bias)
// 128x128 tile, BK=32 halves, double-buffered cp.async with overlap
// (prefetch t+1 committed BEFORE wait_group 1 -> load t+1 flies during MMA t).
// 8 warps, warp tile 64x32, mma m16n8k16 f16 -> f32 accum.
// smem row stride 40 halves (80B, 16B-multiple, conflict-free frag loads).
// Requires: K % 32 == 0, N % 128 == 0. Outputs: Cf (fp32) and/or Ch (fp16).
// ---------------------------------------------------------------------------
#define HBK 32
#define HSM 40

__global__ __launch_bounds__(256, 2) void tgemm_h(
    const __half* __restrict__ A, const __half* __restrict__ B,
    const float* __restrict__ bias, float* __restrict__ Cf,
    __half* __restrict__ Ch,
    int M, int N, int K, int lda, int ldb, int ldc, int act) {
    __shared__ __align__(16) __half As[2][128][HSM];
    __shared__ __align__(16) __half Bs[2][128][HSM];
    const int tid = threadIdx.x;
    const int bm = blockIdx.y * 128, bn = blockIdx.x * 128;
    const int lane = tid & 31, wid = tid >> 5;
    const int wm = (wid >> 2) * 64, wn = (wid & 3) * 32;
    const int g = lane >> 2, t4 = lane & 3;

    float acc[4][4][4];
#pragma unroll
    for (int i = 0; i < 4; i++)
#pragma unroll
        for (int j = 0; j < 4; j++)
#pragma unroll
            for (int k = 0; k < 4; k++) acc[i][j][k] = 0.f;

    const int T = K / HBK;
    const int lr = tid >> 1, lh = (tid & 1) * 16;
    int ga = bm + lr; if (ga >= M) ga = M - 1;
    const int gb = bn + lr;           // N % 128 == 0 -> in range

    // prologue: tile 0
    cp16(&As[0][lr][lh],     A + (size_t)ga * lda + lh);
    cp16(&As[0][lr][lh + 8], A + (size_t)ga * lda + lh + 8);
    cp16(&Bs[0][lr][lh],     B + (size_t)gb * ldb + lh);
    cp16(&Bs[0][lr][lh + 8], B + (size_t)gb * ldb + lh + 8);
    asm volatile("cp.async.commit_group;");

    for (int t = 0; t < T; t++) {
        const int cur = t & 1;
        if (t + 1 < T) {
            const int k0 = (t + 1) * HBK;
            const int nxt = cur ^ 1;
            cp16(&As[nxt][lr][lh],     A + (size_t)ga * lda + k0 + lh);
            cp16(&As[nxt][lr][lh + 8], A + (size_t)ga * lda + k0 + lh + 8);
            cp16(&Bs[nxt][lr][lh],     B + (size_t)gb * ldb + k0 + lh);
            cp16(&Bs[nxt][lr][lh + 8], B + (size_t)gb * ldb + k0 + lh + 8);
            asm volatile("cp.async.commit_group;");
            asm volatile("cp.async.wait_group 1;");
        } else {
            asm volatile("cp.async.wait_group 0;");
        }
        __syncthreads();

#pragma unroll
        for (int ks = 0; ks < 2; ks++) {
            const int kb = ks * 16 + 2 * t4;
            uint32_t af[4][4], bf[4][2];
#pragma unroll
            for (int mt = 0; mt < 4; mt++) {
                const int r = wm + mt * 16;
                af[mt][0] = *(const uint32_t*)&As[cur][r + g][kb];
                af[mt][1] = *(const uint32_t*)&As[cur][r + g + 8][kb];
                af[mt][2] = *(const uint32_t*)&As[cur][r + g][kb + 8];
                af[mt][3] = *(const uint32_t*)&As[cur][r + g + 8][kb + 8];
            }
#pragma unroll
            for (int nt = 0; nt < 4; nt++) {
                bf[nt][0] = *(const uint32_t*)&Bs[cur][wn + nt * 8 + g][kb];
                bf[nt][1] = *(const uint32_t*)&Bs[cur][wn + nt * 8 + g][kb + 8];
            }
#pragma unroll
            for (int mt = 0; mt < 4; mt++)
#pragma unroll
                for (int nt = 0; nt < 4; nt++)
                    mma_f16(acc[mt][nt], af[mt], bf[nt]);
        }
        __syncthreads();
    }

    // epilogue
#pragma unroll
    for (int mt = 0; mt < 4; mt++) {
        const int rA = bm + wm + mt * 16 + g;
        const int rB = rA + 8;
#pragma unroll
        for (int nt = 0; nt < 4; nt++) {
            const int c = bn + wn + nt * 8 + 2 * t4;
            const float b0 = bias ? bias[c] : 0.f;
            const float b1 = bias ? bias[c + 1] : 0.f;
            float v0 = acc[mt][nt][0] + b0, v1 = acc[mt][nt][1] + b1;
            float v2 = acc[mt][nt][2] + b0, v3 = acc[mt][nt][3] + b1;
            if (act == 1) {
                v0 = v0 / (1.f + __expf(-v0));
                v1 = v1 / (1.f + __expf(-v1));
                v2 = v2 / (1.f + __expf(-v2));
                v3 = v3 / (1.f + __expf(-v3));
            }
            if (rA < M) {
                if (Cf) *(float2*)&Cf[(size_t)rA * ldc + c] = make_float2(v0, v1);
                if (Ch) *(__half2*)&Ch[(size_t)rA * ldc + c] = __floats2half2_rn(v0, v1);
            }
            if (rB < M) {
                if (Cf) *(float2*)&Cf[(size_t)rB * ldc + c] = make_float2(v2, v3);
                if (Ch) *(__half2*)&Ch[(size_t)rB * ldc + c] = __floats2half2_rn(v2, v3);
            }
        }
    }
}

// ---------------------------------------------------------------------------
// fp32 -> fp16 conversion
// ---------------------------------------------------------------------------
__global__ void f2h_kernel(const float* __restrict__ src, __half* __restrict__ dst, int n) {
    int i = blockIdx.x * blockDim.x + threadIdx.x;
    if (i < n) dst[i] = __float2half(src[i]);
}

// ---------------------------------------------------------------------------
// Zero pad rows of g_emb / g_emb_h (positions 0..W-2 per batch)
// ---------------------------------------------------------------------------
__global__ void zero_pad_kernel() {
    int idx = blockIdx.x * blockDim.x + threadIdx.x;
    if (idx >= BB * (WW - 1) * EE) return;
    int e = idx & (EE - 1);
    int p = (idx >> 8) % (WW - 1);
    int b = idx / ((WW - 1) * EE);
    size_t o = ((size_t)b * PP + p) * EE + e;
    g_emb[o] = 0.f;
    g_emb_h[o] = __float2half(0.f);
}

// ---------------------------------------------------------------------------
// Layer-1 attention via tensor cores (tf32). One block (128 thr) per (n,h).
// Output written as fp16 (feeds the projection GEMM only).
// ---------------------------------------------------------------------------
#define QS(r, c) s_q[(r) * 33 + (c)]
#define KS(r, c) s_k[(r) * 33 + (c)]
#define VS(r, c) s_v[(r) * 33 + (c)]
#define SC(r, c) s_s[(r) * 66 + (c)]

__global__ __launch_bounds__(128) void attn1_kernel(const float* __restrict__ qkv,
                                                    __half* __restrict__ out_h) {
    __shared__ float s_q[WW * 33], s_k[WW * 33], s_v[WW * 33];
    __shared__ float s_s[WW * 66];
    const int h = blockIdx.x;
    const int n = blockIdx.y;
    const int b = n >> 10, s = n & (SS - 1);
    const int tid = threadIdx.x;
    const int lane = tid & 31, w = tid >> 5;
    const int g = lane >> 2, t4 = lane & 3;

    size_t base = ((size_t)b * PP + s) * TE + h * HD;
    for (int t = tid; t < WW * HD; t += 128) {
        int wpos = t >> 5, d = t & 31;
        size_t r = base + (size_t)wpos * TE + d;
        QS(wpos, d) = __uint_as_float(f2tf(qkv[r]));
        KS(wpos, d) = __uint_as_float(f2tf(qkv[r + EE]));
        VS(wpos, d) = __uint_as_float(f2tf(qkv[r + 2 * EE]));
    }
    __syncthreads();

    // scores: warp w -> rows 16w..16w+15, all 64 cols
    {
        float sacc[8][4];
#pragma unroll
        for (int i = 0; i < 8; i++)
#pragma unroll
            for (int j = 0; j < 4; j++) sacc[i][j] = 0.f;
#pragma unroll
        for (int k0 = 0; k0 < HD; k0 += 8) {
            uint32_t a[4];
            a[0] = __float_as_uint(QS(16 * w + g, k0 + t4));
            a[1] = __float_as_uint(QS(16 * w + g + 8, k0 + t4));
            a[2] = __float_as_uint(QS(16 * w + g, k0 + t4 + 4));
            a[3] = __float_as_uint(QS(16 * w + g + 8, k0 + t4 + 4));
#pragma unroll
            for (int nt = 0; nt < 8; nt++) {
                uint32_t bfr[2];
                bfr[0] = __float_as_uint(KS(nt * 8 + g, k0 + t4));
                bfr[1] = __float_as_uint(KS(nt * 8 + g, k0 + t4 + 4));
                mma_tf32(sacc[nt], a, bfr);
            }
        }
#pragma unroll
        for (int nt = 0; nt < 8; nt++) {
            const int r0 = 16 * w + g, c = nt * 8 + 2 * t4;
            *(float2*)&SC(r0, c)     = make_float2(sacc[nt][0] * ATT_SCALE, sacc[nt][1] * ATT_SCALE);
            *(float2*)&SC(r0 + 8, c) = make_float2(sacc[nt][2] * ATT_SCALE, sacc[nt][3] * ATT_SCALE);
        }
    }
    __syncthreads();

    // softmax: 2 threads per row; write back tf32-rounded probabilities
    {
        const int row = tid >> 1, half_ = tid & 1;
        const int cb = half_ * 32;
        float mx = -1e30f;
#pragma unroll
        for (int j = 0; j < 32; j++) mx = fmaxf(mx, SC(row, cb + j));
        mx = fmaxf(mx, __shfl_xor_sync(0xffffffff, mx, 1));
        float ebuf[32];
        float sum = 0.f;
#pragma unroll
        for (int j = 0; j < 32; j++) {
            ebuf[j] = __expf(SC(row, cb + j) - mx);
            sum += ebuf[j];
        }
        sum += __shfl_xor_sync(0xffffffff, sum, 1);
        float inv = 1.f / sum;
#pragma unroll
        for (int j = 0; j < 32; j++)
            SC(row, cb + j) = __uint_as_float(f2tf(ebuf[j] * inv));
    }
    __syncthreads();

    // O = P V
    {
        float oacc[4][4];
#pragma unroll
        for (int i = 0; i < 4; i++)
#pragma unroll
            for (int j = 0; j < 4; j++) oacc[i][j] = 0.f;
#pragma unroll
        for (int k0 = 0; k0 < WW; k0 += 8) {
            uint32_t a[4];
            a[0] = __float_as_uint(SC(16 * w + g, k0 + t4));
            a[1] = __float_as_uint(SC(16 * w + g + 8, k0 + t4));
            a[2] = __float_as_uint(SC(16 * w + g, k0 + t4 + 4));
            a[3] = __float_as_uint(SC(16 * w + g + 8, k0 + t4 + 4));
#pragma unroll
            for (int nt = 0; nt < 4; nt++) {
                uint32_t bfr[2];
                bfr[0] = __float_as_uint(VS(k0 + t4, nt * 8 + g));
                bfr[1] = __float_as_uint(VS(k0 + t4 + 4, nt * 8 + g));
                mma_tf32(oacc[nt], a, bfr);
            }
        }
        const size_t row0 = ((size_t)n * WW + 16 * w + g) * EE + h * HD;
        const size_t row1 = row0 + 8 * EE;
#pragma unroll
        for (int nt = 0; nt < 4; nt++) {
            const int c = nt * 8 + 2 * t4;
            *(__half2*)&out_h[row0 + c] = __floats2half2_rn(oacc[nt][0], oacc[nt][1]);
            *(__half2*)&out_h[row1 + c] = __floats2half2_rn(oacc[nt][2], oacc[nt][3]);
        }
    }
}

// ---------------------------------------------------------------------------
// Layer-2 attention (pruned): Q fp32 [2048,256], KV fp32 [NROW,512] -> fp16 out
// ---------------------------------------------------------------------------
__global__ __launch_bounds__(64) void attn2_kernel(const float* __restrict__ q2,
                                                   const float* __restrict__ kv,
                                                   __half* __restrict__ out_h) {
    int h = blockIdx.x;
    int n = blockIdx.y;
    int tid = threadIdx.x;
    __shared__ float ks[WW][HD + 1], vs[WW][HD + 1];
    __shared__ float q[HD], p[WW];

    size_t base = (size_t)n * WW * 512 + h * HD;
    for (int t = tid; t < WW * HD; t += 64) {
        int wpos = t >> 5, d = t & 31;
        size_t r = base + (size_t)wpos * 512 + d;
        ks[wpos][d] = kv[r];
        vs[wpos][d] = kv[r + 256];
    }
    if (tid < HD) q[tid] = q2[(size_t)n * EE + h * HD + tid];
    __syncthreads();

    {
        float dsum = 0.f;
#pragma unroll
        for (int d = 0; d < HD; d++) dsum = fmaf(q[d], ks[tid][d], dsum);
        p[tid] = dsum * ATT_SCALE;
    }
    __syncthreads();
    if (tid < 32) {
        float v = fmaxf(p[tid], p[tid + 32]);
#pragma unroll
        for (int o = 16; o > 0; o >>= 1) v = fmaxf(v, __shfl_xor_sync(0xffffffff, v, o));
        float e0 = __expf(p[tid] - v), e1 = __expf(p[tid + 32] - v);
        float sm = e0 + e1;
#pragma unroll
        for (int o = 16; o > 0; o >>= 1) sm += __shfl_xor_sync(0xffffffff, sm, o);
        float inv = 1.f / sm;
        p[tid] = e0 * inv; p[tid + 32] = e1 * inv;
    }
    __syncthreads();
    if (tid < HD) {
        float acc = 0.f;
#pragma unroll
        for (int j = 0; j < WW; j++) acc = fmaf(p[j], vs[j][tid], acc);
        out_h[(size_t)n * EE + h * HD + tid] = __float2half(acc);
    }
}

// ---------------------------------------------------------------------------
// Fused residual-add + LayerNorm; optional fp16 copy of the output.
// mode 0: res row = row; mode 1: res = window view of g_emb.
// ---------------------------------------------------------------------------
__global__ __launch_bounds__(256) void add_ln_kernel(
    const float* __restrict__ a, const float* __restrict__ res,
    const float* __restrict__ gamma, const float* __restrict__ beta,
    float* __restrict__ out, __half* __restrict__ out_h, int mode) {
    int row = blockIdx.x;
    int e = threadIdx.x;
    int lane = e & 31, w = e >> 5;
    __shared__ float ws[8];

    size_t roff;
    if (mode == 0) roff = (size_t)row * EE;
    else {
        int n = row >> 6, wp = row & 63;
        int b = n >> 10, s = n & (SS - 1);
        roff = ((size_t)b * PP + s + wp) * EE;
    }

    float x = a[(size_t)row * EE + e] + res[roff + e];

    float s1 = x;
#pragma unroll
    for (int o = 16; o > 0; o >>= 1) s1 += __shfl_xor_sync(0xffffffff, s1, o);
    if (lane == 0) ws[w] = s1;
    __syncthreads();
    float tot = 0.f;
#pragma unroll
    for (int i = 0; i < 8; i++) tot += ws[i];
    float mean = tot * (1.f / EE);
    __syncthreads();

    float d = x - mean;
    float s2 = d * d;
#pragma unroll
    for (int o = 16; o > 0; o >>= 1) s2 += __shfl_xor_sync(0xffffffff, s2, o);
    if (lane == 0) ws[w] = s2;
    __syncthreads();
    float tot2 = 0.f;
#pragma unroll
    for (int i = 0; i < 8; i++) tot2 += ws[i];
    float var = tot2 * (1.f / EE);
    float y = d * rsqrtf(var + LN_EPS) * gamma[e] + beta[e];
    out[(size_t)row * EE + e] = y;
    if (out_h) out_h[(size_t)row * EE + e] = __float2half(y);
}

// ---------------------------------------------------------------------------
// Gather last window rows -> fp32 + fp16
// ---------------------------------------------------------------------------
__global__ void gather_last_kernel(const float* __restrict__ x2,
                                   float* __restrict__ xlast,
                                   __half* __restrict__ xlast_h) {
    int idx = blockIdx.x * blockDim.x + threadIdx.x;
    if (idx >= NWIN * EE) return;
    int n = idx >> 8, e = idx & 255;
    float v = x2[((size_t)n * WW + (WW - 1)) * EE + e];
    xlast[idx] = v;
    xlast_h[idx] = __float2half(v);
}

// ---------------------------------------------------------------------------
// Head
// ---------------------------------------------------------------------------
__global__ void head_kernel(const float* __restrict__ y,
                            const float* __restrict__ hw,
                            const float* __restrict__ hb,
                            float* __restrict__ out) {
    int idx = blockIdx.x * blockDim.x + threadIdx.x;
    if (idx >= NWIN * OUTD) return;
    int n = idx / OUTD, o = idx % OUTD;
    const float* yr = y + (size_t)n * EE;
    const float* wr = hw + (size_t)o * EE;
    float acc = hb[o];
#pragma unroll 8
    for (int k = 0; k < EE; k++) acc = fmaf(yr[k], wr[k], acc);
    out[idx] = acc;
}

// ---------------------------------------------------------------------------
// Host launch
// ---------------------------------------------------------------------------
static inline dim3 tgrid(int M, int N) {
    return dim3(N / 128, (M + 127) / 128);
}
static inline void f2h(const float* s, __half* d, int n) {
    f2h_kernel<<<(n + 255) / 256, 256>>>(s, d, n);
}

extern "C" void kernel_launch(void* const* d_in, const int* in_sizes, int n_in,
                              void* d_out, int out_size) {
    const float* inputs     = (const float*)d_in[0];
    const float* embed_w    = (const float*)d_in[1];
    const float* embed_b    = (const float*)d_in[2];
    const float* qkv_w      = (const float*)d_in[3];
    const float* qkv_b      = (const float*)d_in[4];
    const float* attn_out_w = (const float*)d_in[5];
    const float* attn_out_b = (const float*)d_in[6];
    const float* ln1_g      = (const float*)d_in[7];
    const float* ln1_b      = (const float*)d_in[8];
    const float* ffn1_w     = (const float*)d_in[9];
    const float* ffn1_b     = (const float*)d_in[10];
    const float* ffn2_w     = (const float*)d_in[11];
    const float* ffn2_b     = (const float*)d_in[12];
    const float* ln2_g      = (const float*)d_in[13];
    const float* ln2_b      = (const float*)d_in[14];
    const float* head_w     = (const float*)d_in[15];
    const float* head_b     = (const float*)d_in[16];
    float* out = (float*)d_out;

    float *emb, *qkv, *bufA, *bufB, *kv2, *xlast, *r1, *r2;
    __half *in_h, *ew_h, *qw_h, *aw_h, *f1w_h, *f2w_h;
    __half *emb_h, *attn_h, *x_h, *ffh_h, *xlast_h, *r1_h, *r3_h;
    cudaGetSymbolAddress((void**)&emb,   g_emb);
    cudaGetSymbolAddress((void**)&qkv,   g_qkv);
    cudaGetSymbolAddress((void**)&bufA,  g_bufA);
    cudaGetSymbolAddress((void**)&bufB,  g_bufB);
    cudaGetSymbolAddress((void**)&kv2,   g_kv2);
    cudaGetSymbolAddress((void**)&xlast, g_xlast);
    cudaGetSymbolAddress((void**)&r1,    g_r1);
    cudaGetSymbolAddress((void**)&r2,    g_r2);
    cudaGetSymbolAddress((void**)&in_h,   g_in_h);
    cudaGetSymbolAddress((void**)&ew_h,   g_ew_h);
    cudaGetSymbolAddress((void**)&qw_h,   g_qw_h);
    cudaGetSymbolAddress((void**)&aw_h,   g_aw_h);
    cudaGetSymbolAddress((void**)&f1w_h,  g_f1w_h);
    cudaGetSymbolAddress((void**)&f2w_h,  g_f2w_h);
    cudaGetSymbolAddress((void**)&emb_h,  g_emb_h);
    cudaGetSymbolAddress((void**)&attn_h, g_attn_h);
    cudaGetSymbolAddress((void**)&x_h,    g_x_h);
    cudaGetSymbolAddress((void**)&ffh_h,  g_ffh_h);
    cudaGetSymbolAddress((void**)&xlast_h, g_xlast_h);
    cudaGetSymbolAddress((void**)&r1_h,   g_r1_h);
    cudaGetSymbolAddress((void**)&r3_h,   g_r3_h);

    // 0. fp16 conversions of inputs + all weights
    f2h(inputs,     in_h,  BB * SS * FIN);
    f2h(embed_w,    ew_h,  EE * FIN);
    f2h(qkv_w,      qw_h,  2 * TE * EE);
    f2h(attn_out_w, aw_h,  2 * EE * EE);
    f2h(ffn1_w,     f1w_h, 2 * FF * EE);
    f2h(ffn2_w,     f2w_h, 2 * EE * FF);
    zero_pad_kernel<<<(BB * (WW - 1) * EE + 255) / 256, 256>>>();

    // 1. embedding (per batch): fp32 + fp16 outputs
    for (int b = 0; b < BB; b++) {
        size_t off = ((size_t)b * PP + (WW - 1)) * EE;
        tgemm_h<<<tgrid(SS, EE), 256>>>(in_h + (size_t)b * SS * FIN, ew_h, embed_b,
                                        emb + off, emb_h + off,
                                        SS, EE, FIN, FIN, FIN, EE, 0);
    }
    // 2. Layer-1 QKV (shared): [2174,256] x [768,256]^T -> fp32
    tgemm_h<<<tgrid(BB * PP, TE), 256>>>(emb_h, qw_h, qkv_b, qkv, (__half*)0,
                                         BB * PP, TE, EE, EE, EE, TE, 0);
    // 3. attention -> fp16 attn_h
    attn1_kernel<<<dim3(NH, NWIN), 128>>>(qkv, attn_h);
    // 4. attn-out proj -> fp32 bufB
    tgemm_h<<<tgrid(NROW, EE), 256>>>(attn_h, aw_h, attn_out_b, bufB, (__half*)0,
                                      NROW, EE, EE, EE, EE, EE, 0);
    // 5. x1 = LN1(emb_window + bufB) -> bufA (fp32) + x_h (fp16)
    add_ln_kernel<<<NROW, 256>>>(bufB, emb, ln1_g, ln1_b, bufA, x_h, 1);
    // 6. FFN hidden (silu) -> fp16 only
    tgemm_h<<<tgrid(NROW, FF), 256>>>(x_h, f1w_h, ffn1_b, (float*)0, ffh_h,
                                      NROW, FF, EE, EE, EE, FF, 1);
    // 7. FFN out -> fp32 bufB
    tgemm_h<<<tgrid(NROW, EE), 256>>>(ffh_h, f2w_h, ffn2_b, bufB, (__half*)0,
                                      NROW, EE, FF, FF, FF, EE, 0);
    // 8. x2 = LN2(x1 + bufB) -> bufA + x_h
    add_ln_kernel<<<NROW, 256>>>(bufB, bufA, ln2_g, ln2_b, bufA, x_h, 0);

    // ---- Layer 2 (output pruned) ----
    // 9. gather last rows; Q only for last rows
    gather_last_kernel<<<(NWIN * EE + 255) / 256, 256>>>(bufA, xlast, xlast_h);
    tgemm_h<<<tgrid(NWIN, EE), 256>>>(xlast_h, qw_h + (size_t)TE * EE, qkv_b + TE,
                                      r2, (__half*)0, NWIN, EE, EE, EE, EE, EE, 0);
    // 10. KV for all rows -> fp32 kv2 [NROW,512]
    tgemm_h<<<tgrid(NROW, 512), 256>>>(x_h, qw_h + (size_t)TE * EE + (size_t)EE * EE,
                                       qkv_b + TE + EE, kv2, (__half*)0,
                                       NROW, 512, EE, EE, EE, 512, 0);
    // 11. attention -> fp16 r1_h
    attn2_kernel<<<dim3(NH, NWIN), 64>>>(r2, kv2, r1_h);
    // 12. proj -> fp32 r2
    tgemm_h<<<tgrid(NWIN, EE), 256>>>(r1_h, aw_h + (size_t)EE * EE, attn_out_b + EE,
                                      r2, (__half*)0, NWIN, EE, EE, EE, EE, EE, 0);
    // 13. y = LN1_l2(xlast + r2) -> r1 + r1_h
    add_ln_kernel<<<NWIN, 256>>>(r2, xlast, ln1_g + EE, ln1_b + EE, r1, r1_h, 0);
    // 14. h2 = silu(y @ W1^T) -> fp16 r3_h
    tgemm_h<<<tgrid(NWIN, FF), 256>>>(r1_h, f1w_h + (size_t)FF * EE, ffn1_b + FF,
                                      (float*)0, r3_h, NWIN, FF, EE, EE, EE, FF, 1);
    // 15. f2 -> fp32 r2
    tgemm_h<<<tgrid(NWIN, EE), 256>>>(r3_h, f2w_h + (size_t)EE * FF, ffn2_b + EE,
                                      r2, (__half*)0, NWIN, EE, FF, FF, FF, EE, 0);
    // 16. y2 = LN2_l2(y + f2) -> r1
    add_ln_kernel<<<NWIN, 256>>>(r2, r1, ln2_g + EE, ln2_b + EE, r1, (__half*)0, 0);
    // 17. head -> d_out
    head_kernel<<<(NWIN * OUTD + 255) / 256, 256>>>(r1, head_w, head_b, out);
}

// round 12
// speedup vs baseline: 1.8652x; 1.1107x over previous
#include <cuda_runtime.h>
#include <cuda_fp16.h>
#include <math.h>
#include <stdint.h>

// ---------------------------------------------------------------------------
// Problem constants
// ---------------------------------------------------------------------------
#define BB 2
#define SS 1024
#define WW 64
#define PP (SS + WW - 1)   // 1087
#define EE 256
#define FIN 64
#define FF 1024
#define TE 768
#define NH 8
#define HD 32
#define NWIN (BB * SS)     // 2048
#define NROW (NWIN * WW)   // 131072
#define OUTD 10
#define LN_EPS 1e-5f
#define ATT_SCALE 0.17677669529663687f

// ---------------------------------------------------------------------------
// Scratch (fp32)
// ---------------------------------------------------------------------------
__device__ float g_emb  [BB * PP * EE];
__device__ float g_bufA [(size_t)NROW * EE];   // x1 / x2
__device__ float g_bufB [(size_t)NROW * EE];   // GEMM fp32 outputs
__device__ float g_xlast[NWIN * EE];
__device__ float g_r1   [NWIN * EE];
__device__ float g_r2   [NWIN * EE];

// Scratch (fp16)
__device__ __half g_in_h  [BB * SS * FIN];
__device__ __half g_ew_h  [EE * FIN];
__device__ __half g_qw_h  [2 * TE * EE];
__device__ __half g_aw_h  [2 * EE * EE];
__device__ __half g_f1w_h [2 * FF * EE];
__device__ __half g_f2w_h [2 * EE * FF];
__device__ __half g_emb_h [BB * PP * EE];
__device__ __half g_qkv_h [BB * PP * TE];
__device__ __half g_attn_h[(size_t)NROW * EE];
__device__ __half g_x_h   [(size_t)NROW * EE];
__device__ __half g_ffh_h [(size_t)NROW * FF];
__device__ __half g_kv2_h [(size_t)NROW * 512];
__device__ __half g_xlast_h[NWIN * EE];
__device__ __half g_r1_h  [NWIN * EE];
__device__ __half g_r3_h  [NWIN * FF];

// ---------------------------------------------------------------------------
// MMA helpers
// ---------------------------------------------------------------------------
__device__ __forceinline__ void mma_f16(float* c, const uint32_t* a, const uint32_t* b) {
    asm volatile(
        "mma.sync.aligned.m16n8k16.row.col.f32.f16.f16.f32 "
        "{%0,%1,%2,%3},{%4,%5,%6,%7},{%8,%9},{%0,%1,%2,%3};"
        : "+f"(c[0]), "+f"(c[1]), "+f"(c[2]), "+f"(c[3])
        : "r"(a[0]), "r"(a[1]), "r"(a[2]), "r"(a[3]), "r"(b[0]), "r"(b[1]));
}

__device__ __forceinline__ void cp16(void* s, const void* g) {
    uint32_t sa = (uint32_t)__cvta_generic_to_shared(s);
    asm volatile("cp.async.cg.shared.global [%0], [%1], 16;" :: "r"(sa), "l"(g));
}

__device__ __forceinline__ void ldsm4(uint32_t* r, uint32_t addr) {
    asm volatile("ldmatrix.sync.aligned.m8n8.x4.shared.b16 {%0,%1,%2,%3}, [%4];"
        : "=r"(r[0]), "=r"(r[1]), "=r"(r[2]), "=r"(r[3]) : "r"(addr));
}

// ---------------------------------------------------------------------------
// FP16 tensor-core GEMM (NT): C = act(A[M,K] * B[N,K]^T + bias)
// 128x128 tile, BK=32, double-buffered cp.async with load/compute overlap.
// Fragments via ldmatrix.x4 (6 LDSM per 16 MMAs). smem row stride 40 halves
// (80B): 8 rows span all 32 banks exactly once -> conflict-free LDSM.
// Requires: K % 32 == 0, N % 128 == 0. Outputs: Cf (fp32) and/or Ch (fp16).
// ---------------------------------------------------------------------------
#define HBK 32
#define HSM 40
#define HBUF (128 * HSM * 2)   // bytes per stage

__global__ __launch_bounds__(256, 2) void tgemm_h(
    const __half* __restrict__ A, const __half* __restrict__ B,
    const float* __restrict__ bias, float* __restrict__ Cf,
    __half* __restrict__ Ch,
    int M, int N, int K, int lda, int ldb, int ldc, int act) {
    __shared__ __align__(16) __half As[2][128][HSM];
    __shared__ __align__(16) __half Bs[2][128][HSM];
    const int tid = threadIdx.x;
    const int bm = blockIdx.y * 128, bn = blockIdx.x * 128;
    const int lane = tid & 31, wid = tid >> 5;
    const int wm = (wid >> 2) * 64, wn = (wid & 3) * 32;
    const int g = lane >> 2, t4 = lane & 3;
    const int quad = lane >> 3, r8 = lane & 7;
    // ldmatrix lane->row/col mapping (A: a0..a3; B pair: b_lo0,b_lo1,b_hi0,b_hi1)
    const int a_row = (quad & 1) * 8 + r8, a_colq = (quad >> 1) * 8;
    const int b_row = (quad >> 1) * 8 + r8, b_colq = (quad & 1) * 8;
    const uint32_t sA = (uint32_t)__cvta_generic_to_shared(&As[0][0][0]);
    const uint32_t sB = (uint32_t)__cvta_generic_to_shared(&Bs[0][0][0]);

    float acc[4][4][4];
#pragma unroll
    for (int i = 0; i < 4; i++)
#pragma unroll
        for (int j = 0; j < 4; j++)
#pragma unroll
            for (int k = 0; k < 4; k++) acc[i][j][k] = 0.f;

    const int T = K / HBK;
    const int lr = tid >> 1, lh = (tid & 1) * 16;
    int ga = bm + lr; if (ga >= M) ga = M - 1;
    const int gb = bn + lr;

    cp16(&As[0][lr][lh],     A + (size_t)ga * lda + lh);
    cp16(&As[0][lr][lh + 8], A + (size_t)ga * lda + lh + 8);
    cp16(&Bs[0][lr][lh],     B + (size_t)gb * ldb + lh);
    cp16(&Bs[0][lr][lh + 8], B + (size_t)gb * ldb + lh + 8);
    asm volatile("cp.async.commit_group;");

    for (int t = 0; t < T; t++) {
        const int cur = t & 1;
        if (t + 1 < T) {
            const int k0 = (t + 1) * HBK;
            const int nxt = cur ^ 1;
            cp16(&As[nxt][lr][lh],     A + (size_t)ga * lda + k0 + lh);
            cp16(&As[nxt][lr][lh + 8], A + (size_t)ga * lda + k0 + lh + 8);
            cp16(&Bs[nxt][lr][lh],     B + (size_t)gb * ldb + k0 + lh);
            cp16(&Bs[nxt][lr][lh + 8], B + (size_t)gb * ldb + k0 + lh + 8);
            asm volatile("cp.async.commit_group;");
            asm volatile("cp.async.wait_group 1;");
        } else {
            asm volatile("cp.async.wait_group 0;");
        }
        __syncthreads();

        const uint32_t aBase = sA + cur * HBUF;
        const uint32_t bBase = sB + cur * HBUF;
#pragma unroll
        for (int ks = 0; ks < 2; ks++) {
            const int kc = ks * 16;
            uint32_t af[4][4], bf[4][2];
#pragma unroll
            for (int mt = 0; mt < 4; mt++)
                ldsm4(af[mt], aBase + ((wm + mt * 16 + a_row) * HSM + kc + a_colq) * 2);
#pragma unroll
            for (int ntp = 0; ntp < 2; ntp++) {
                uint32_t bt[4];
                ldsm4(bt, bBase + ((wn + ntp * 16 + b_row) * HSM + kc + b_colq) * 2);
                bf[2 * ntp][0] = bt[0]; bf[2 * ntp][1] = bt[1];
                bf[2 * ntp + 1][0] = bt[2]; bf[2 * ntp + 1][1] = bt[3];
            }
#pragma unroll
            for (int mt = 0; mt < 4; mt++)
#pragma unroll
                for (int nt = 0; nt < 4; nt++)
                    mma_f16(acc[mt][nt], af[mt], bf[nt]);
        }
        __syncthreads();
    }

#pragma unroll
    for (int mt = 0; mt < 4; mt++) {
        const int rA = bm + wm + mt * 16 + g;
        const int rB = rA + 8;
#pragma unroll
        for (int nt = 0; nt < 4; nt++) {
            const int c = bn + wn + nt * 8 + 2 * t4;
            const float b0 = bias ? bias[c] : 0.f;
            const float b1 = bias ? bias[c + 1] : 0.f;
            float v0 = acc[mt][nt][0] + b0, v1 = acc[mt][nt][1] + b1;
            float v2 = acc[mt][nt][2] + b0, v3 = acc[mt][nt][3] + b1;
            if (act == 1) {
                v0 = v0 / (1.f + __expf(-v0));
                v1 = v1 / (1.f + __expf(-v1));
                v2 = v2 / (1.f + __expf(-v2));
                v3 = v3 / (1.f + __expf(-v3));
            }
            if (rA < M) {
                if (Cf) *(float2*)&Cf[(size_t)rA * ldc + c] = make_float2(v0, v1);
                if (Ch) *(__half2*)&Ch[(size_t)rA * ldc + c] = __floats2half2_rn(v0, v1);
            }
            if (rB < M) {
                if (Cf) *(float2*)&Cf[(size_t)rB * ldc + c] = make_float2(v2, v3);
                if (Ch) *(__half2*)&Ch[(size_t)rB * ldc + c] = __floats2half2_rn(v2, v3);
            }
        }
    }
}

// ---------------------------------------------------------------------------
// fp32 -> fp16 (vectorized)
// ---------------------------------------------------------------------------
__global__ void f2h2_kernel(const float2* __restrict__ src, __half2* __restrict__ dst, int n2) {
    int i = blockIdx.x * blockDim.x + threadIdx.x;
    if (i < n2) { float2 v = src[i]; dst[i] = __floats2half2_rn(v.x, v.y); }
}

// ---------------------------------------------------------------------------
// Zero pad rows of g_emb / g_emb_h
// ---------------------------------------------------------------------------
__global__ void zero_pad_kernel() {
    int idx = blockIdx.x * blockDim.x + threadIdx.x;
    if (idx >= BB * (WW - 1) * EE) return;
    int e = idx & (EE - 1);
    int p = (idx >> 8) % (WW - 1);
    int b = idx / ((WW - 1) * EE);
    size_t o = ((size_t)b * PP + p) * EE + e;
    g_emb[o] = 0.f;
    g_emb_h[o] = __float2half(0.f);
}

// ---------------------------------------------------------------------------
// Layer-1 attention, full fp16 MMA. One block (128 thr, 4 warps) per (n,h).
// QKV read fp16; scores fp32 accum -> softmax fp32 -> P fp16 -> PV fp16 MMA.
// ---------------------------------------------------------------------------
#define QS(r, c) s_q[(r) * 40 + (c)]
#define KS(r, c) s_k[(r) * 40 + (c)]
#define VT(d, c) s_vt[(d) * 72 + (c)]
#define SC(r, c) s_s[(r) * 66 + (c)]
#define PS(r, c) s_p[(r) * 72 + (c)]

__global__ __launch_bounds__(128) void attn1_kernel(const __half* __restrict__ qkv,
                                                    __half* __restrict__ out_h) {
    __shared__ __half s_q[WW * 40], s_k[WW * 40];
    __shared__ __half s_vt[HD * 72];          // V transposed: [d][w]
    __shared__ float  s_s[WW * 66];
    __shared__ __half s_p[WW * 72];
    const int h = blockIdx.x;
    const int n = blockIdx.y;
    const int b = n >> 10, s = n & (SS - 1);
    const int tid = threadIdx.x;
    const int lane = tid & 31, w = tid >> 5;
    const int g = lane >> 2, t4 = lane & 3;

    size_t base = ((size_t)b * PP + s) * TE + h * HD;
    for (int t = tid; t < WW * HD / 2; t += 128) {
        int wpos = t >> 4, wd = (t & 15) * 2;
        size_t r = base + (size_t)wpos * TE + wd;
        __half2 qv = *(const __half2*)&qkv[r];
        __half2 kv = *(const __half2*)&qkv[r + EE];
        __half2 vv = *(const __half2*)&qkv[r + 2 * EE];
        *(__half2*)&QS(wpos, wd) = qv;
        *(__half2*)&KS(wpos, wd) = kv;
        VT(wd, wpos) = vv.x;
        VT(wd + 1, wpos) = vv.y;
    }
    __syncthreads();

    // scores = Q K^T (64x64x32): warp w -> rows 16w..16w+15
    {
        float sacc[8][4];
#pragma unroll
        for (int i = 0; i < 8; i++)
#pragma unroll
            for (int j = 0; j < 4; j++) sacc[i][j] = 0.f;
#pragma unroll
        for (int k0 = 0; k0 < HD; k0 += 16) {
            uint32_t a[4];
            a[0] = *(const uint32_t*)&QS(16 * w + g, k0 + 2 * t4);
            a[1] = *(const uint32_t*)&QS(16 * w + g + 8, k0 + 2 * t4);
            a[2] = *(const uint32_t*)&QS(16 * w + g, k0 + 8 + 2 * t4);
            a[3] = *(const uint32_t*)&QS(16 * w + g + 8, k0 + 8 + 2 * t4);
#pragma unroll
            for (int nt = 0; nt < 8; nt++) {
                uint32_t bfr[2];
                bfr[0] = *(const uint32_t*)&KS(nt * 8 + g, k0 + 2 * t4);
                bfr[1] = *(const uint32_t*)&KS(nt * 8 + g, k0 + 8 + 2 * t4);
                mma_f16(sacc[nt], a, bfr);
            }
        }
#pragma unroll
        for (int nt = 0; nt < 8; nt++) {
            const int r0 = 16 * w + g, c = nt * 8 + 2 * t4;
            *(float2*)&SC(r0, c)     = make_float2(sacc[nt][0] * ATT_SCALE, sacc[nt][1] * ATT_SCALE);
            *(float2*)&SC(r0 + 8, c) = make_float2(sacc[nt][2] * ATT_SCALE, sacc[nt][3] * ATT_SCALE);
        }
    }
    __syncthreads();

    // softmax (fp32), P written fp16
    {
        const int row = tid >> 1, half_ = tid & 1;
        const int cb = half_ * 32;
        float mx = -1e30f;
#pragma unroll
        for (int j = 0; j < 32; j++) mx = fmaxf(mx, SC(row, cb + j));
        mx = fmaxf(mx, __shfl_xor_sync(0xffffffff, mx, 1));
        float ebuf[32];
        float sum = 0.f;
#pragma unroll
        for (int j = 0; j < 32; j++) {
            ebuf[j] = __expf(SC(row, cb + j) - mx);
            sum += ebuf[j];
        }
        sum += __shfl_xor_sync(0xffffffff, sum, 1);
        float inv = 1.f / sum;
#pragma unroll
        for (int j = 0; j < 32; j++)
            PS(row, cb + j) = __float2half(ebuf[j] * inv);
    }
    __syncthreads();

    // O = P V (64x32x64) fp16 MMA; B from transposed V
    {
        float oacc[4][4];
#pragma unroll
        for (int i = 0; i < 4; i++)
#pragma unroll
            for (int j = 0; j < 4; j++) oacc[i][j] = 0.f;
#pragma unroll
        for (int k0 = 0; k0 < WW; k0 += 16) {
            uint32_t a[4];
            a[0] = *(const uint32_t*)&PS(16 * w + g, k0 + 2 * t4);
            a[1] = *(const uint32_t*)&PS(16 * w + g + 8, k0 + 2 * t4);
            a[2] = *(const uint32_t*)&PS(16 * w + g, k0 + 8 + 2 * t4);
            a[3] = *(const uint32_t*)&PS(16 * w + g + 8, k0 + 8 + 2 * t4);
#pragma unroll
            for (int nt = 0; nt < 4; nt++) {
                uint32_t bfr[2];
                bfr[0] = *(const uint32_t*)&VT(nt * 8 + g, k0 + 2 * t4);
                bfr[1] = *(const uint32_t*)&VT(nt * 8 + g, k0 + 8 + 2 * t4);
                mma_f16(oacc[nt], a, bfr);
            }
        }
        const size_t row0 = ((size_t)n * WW + 16 * w + g) * EE + h * HD;
        const size_t row1 = row0 + 8 * EE;
#pragma unroll
        for (int nt = 0; nt < 4; nt++) {
            const int c = nt * 8 + 2 * t4;
            *(__half2*)&out_h[row0 + c] = __floats2half2_rn(oacc[nt][0], oacc[nt][1]);
            *(__half2*)&out_h[row1 + c] = __floats2half2_rn(oacc[nt][2], oacc[nt][3]);
        }
    }
}

// ---------------------------------------------------------------------------
// Layer-2 attention (pruned): Q fp32 [2048,256], KV fp16 [NROW,512] -> fp16
// ---------------------------------------------------------------------------
__global__ __launch_bounds__(64) void attn2_kernel(const float* __restrict__ q2,
                                                   const __half* __restrict__ kv,
                                                   __half* __restrict__ out_h) {
    int h = blockIdx.x;
    int n = blockIdx.y;
    int tid = threadIdx.x;
    __shared__ float ks[WW][HD + 1], vs[WW][HD + 1];
    __shared__ float q[HD], p[WW];

    size_t base = (size_t)n * WW * 512 + h * HD;
    for (int t = tid; t < WW * HD; t += 64) {
        int wpos = t >> 5, d = t & 31;
        size_t r = base + (size_t)wpos * 512 + d;
        ks[wpos][d] = __half2float(kv[r]);
        vs[wpos][d] = __half2float(kv[r + 256]);
    }
    if (tid < HD) q[tid] = q2[(size_t)n * EE + h * HD + tid];
    __syncthreads();

    {
        float dsum = 0.f;
#pragma unroll
        for (int d = 0; d < HD; d++) dsum = fmaf(q[d], ks[tid][d], dsum);
        p[tid] = dsum * ATT_SCALE;
    }
    __syncthreads();
    if (tid < 32) {
        float v = fmaxf(p[tid], p[tid + 32]);
#pragma unroll
        for (int o = 16; o > 0; o >>= 1) v = fmaxf(v, __shfl_xor_sync(0xffffffff, v, o));
        float e0 = __expf(p[tid] - v), e1 = __expf(p[tid + 32] - v);
        float sm = e0 + e1;
#pragma unroll
        for (int o = 16; o > 0; o >>= 1) sm += __shfl_xor_sync(0xffffffff, sm, o);
        float inv = 1.f / sm;
        p[tid] = e0 * inv; p[tid + 32] = e1 * inv;
    }
    __syncthreads();
    if (tid < HD) {
        float acc = 0.f;
#pragma unroll
        for (int j = 0; j < WW; j++) acc = fmaf(p[j], vs[j][tid], acc);
        out_h[(size_t)n * EE + h * HD + tid] = __float2half(acc);
    }
}

// ---------------------------------------------------------------------------
// Fused residual-add + LayerNorm; optional fp16 copy.
// mode 0: res row = row; mode 1: res = window view of g_emb.
// ---------------------------------------------------------------------------
__global__ __launch_bounds__(256) void add_ln_kernel(
    const float* __restrict__ a, const float* __restrict__ res,
    const float* __restrict__ gamma, const float* __restrict__ beta,
    float* __restrict__ out, __half* __restrict__ out_h, int mode) {
    int row = blockIdx.x;
    int e = threadIdx.x;
    int lane = e & 31, w = e >> 5;
    __shared__ float ws[8];

    size_t roff;
    if (mode == 0) roff = (size_t)row * EE;
    else {
        int n = row >> 6, wp = row & 63;
        int b = n >> 10, s = n & (SS - 1);
        roff = ((size_t)b * PP + s + wp) * EE;
    }

    float x = a[(size_t)row * EE + e] + res[roff + e];

    float s1 = x;
#pragma unroll
    for (int o = 16; o > 0; o >>= 1) s1 += __shfl_xor_sync(0xffffffff, s1, o);
    if (lane == 0) ws[w] = s1;
    __syncthreads();
    float tot = 0.f;
#pragma unroll
    for (int i = 0; i < 8; i++) tot += ws[i];
    float mean = tot * (1.f / EE);
    __syncthreads();

    float d = x - mean;
    float s2 = d * d;
#pragma unroll
    for (int o = 16; o > 0; o >>= 1) s2 += __shfl_xor_sync(0xffffffff, s2, o);
    if (lane == 0) ws[w] = s2;
    __syncthreads();
    float tot2 = 0.f;
#pragma unroll
    for (int i = 0; i < 8; i++) tot2 += ws[i];
    float var = tot2 * (1.f / EE);
    float y = d * rsqrtf(var + LN_EPS) * gamma[e] + beta[e];
    out[(size_t)row * EE + e] = y;
    if (out_h) out_h[(size_t)row * EE + e] = __float2half(y);
}

// ---------------------------------------------------------------------------
// Gather last window rows -> fp32 + fp16
// ---------------------------------------------------------------------------
__global__ void gather_last_kernel(const float* __restrict__ x2,
                                   float* __restrict__ xlast,
                                   __half* __restrict__ xlast_h) {
    int idx = blockIdx.x * blockDim.x + threadIdx.x;
    if (idx >= NWIN * EE) return;
    int n = idx >> 8, e = idx & 255;
    float v = x2[((size_t)n * WW + (WW - 1)) * EE + e];
    xlast[idx] = v;
    xlast_h[idx] = __float2half(v);
}

// ---------------------------------------------------------------------------
// Head
// ---------------------------------------------------------------------------
__global__ void head_kernel(const float* __restrict__ y,
                            const float* __restrict__ hw,
                            const float* __restrict__ hb,
                            float* __restrict__ out) {
    int idx = blockIdx.x * blockDim.x + threadIdx.x;
    if (idx >= NWIN * OUTD) return;
    int n = idx / OUTD, o = idx % OUTD;
    const float* yr = y + (size_t)n * EE;
    const float* wr = hw + (size_t)o * EE;
    float acc = hb[o];
#pragma unroll 8
    for (int k = 0; k < EE; k++) acc = fmaf(yr[k], wr[k], acc);
    out[idx] = acc;
}

// ---------------------------------------------------------------------------
// Host launch
// ---------------------------------------------------------------------------
static inline dim3 tgrid(int M, int N) {
    return dim3(N / 128, (M + 127) / 128);
}
static inline void f2h(const float* s, __half* d, int n) {
    f2h2_kernel<<<(n / 2 + 255) / 256, 256>>>((const float2*)s, (__half2*)d, n / 2);
}

extern "C" void kernel_launch(void* const* d_in, const int* in_sizes, int n_in,
                              void* d_out, int out_size) {
    const float* inputs     = (const float*)d_in[0];
    const float* embed_w    = (const float*)d_in[1];
    const float* embed_b    = (const float*)d_in[2];
    const float* qkv_w      = (const float*)d_in[3];
    const float* qkv_b      = (const float*)d_in[4];
    const float* attn_out_w = (const float*)d_in[5];
    const float* attn_out_b = (const float*)d_in[6];
    const float* ln1_g      = (const float*)d_in[7];
    const float* ln1_b      = (const float*)d_in[8];
    const float* ffn1_w     = (const float*)d_in[9];
    const float* ffn1_b     = (const float*)d_in[10];
    const float* ffn2_w     = (const float*)d_in[11];
    const float* ffn2_b     = (const float*)d_in[12];
    const float* ln2_g      = (const float*)d_in[13];
    const float* ln2_b      = (const float*)d_in[14];
    const float* head_w     = (const float*)d_in[15];
    const float* head_b     = (const float*)d_in[16];
    float* out = (float*)d_out;

    float *emb, *bufA, *bufB, *xlast, *r1, *r2;
    __half *in_h, *ew_h, *qw_h, *aw_h, *f1w_h, *f2w_h;
    __half *emb_h, *qkv_h, *attn_h, *x_h, *ffh_h, *kv2_h, *xlast_h, *r1_h, *r3_h;
    cudaGetSymbolAddress((void**)&emb,   g_emb);
    cudaGetSymbolAddress((void**)&bufA,  g_bufA);
    cudaGetSymbolAddress((void**)&bufB,  g_bufB);
    cudaGetSymbolAddress((void**)&xlast, g_xlast);
    cudaGetSymbolAddress((void**)&r1,    g_r1);
    cudaGetSymbolAddress((void**)&r2,    g_r2);
    cudaGetSymbolAddress((void**)&in_h,   g_in_h);
    cudaGetSymbolAddress((void**)&ew_h,   g_ew_h);
    cudaGetSymbolAddress((void**)&qw_h,   g_qw_h);
    cudaGetSymbolAddress((void**)&aw_h,   g_aw_h);
    cudaGetSymbolAddress((void**)&f1w_h,  g_f1w_h);
    cudaGetSymbolAddress((void**)&f2w_h,  g_f2w_h);
    cudaGetSymbolAddress((void**)&emb_h,  g_emb_h);
    cudaGetSymbolAddress((void**)&qkv_h,  g_qkv_h);
    cudaGetSymbolAddress((void**)&attn_h, g_attn_h);
    cudaGetSymbolAddress((void**)&x_h,    g_x_h);
    cudaGetSymbolAddress((void**)&ffh_h,  g_ffh_h);
    cudaGetSymbolAddress((void**)&kv2_h,  g_kv2_h);
    cudaGetSymbolAddress((void**)&xlast_h, g_xlast_h);
    cudaGetSymbolAddress((void**)&r1_h,   g_r1_h);
    cudaGetSymbolAddress((void**)&r3_h,   g_r3_h);

    // 0. fp16 conversions
    f2h(inputs,     in_h,  BB * SS * FIN);
    f2h(embed_w,    ew_h,  EE * FIN);
    f2h(qkv_w,      qw_h,  2 * TE * EE);
    f2h(attn_out_w, aw_h,  2 * EE * EE);
    f2h(ffn1_w,     f1w_h, 2 * FF * EE);
    f2h(ffn2_w,     f2w_h, 2 * EE * FF);
    zero_pad_kernel<<<(BB * (WW - 1) * EE + 255) / 256, 256>>>();

    // 1. embedding (per batch)
    for (int b = 0; b < BB; b++) {
        size_t off = ((size_t)b * PP + (WW - 1)) * EE;
        tgemm_h<<<tgrid(SS, EE), 256>>>(in_h + (size_t)b * SS * FIN, ew_h, embed_b,
                                        emb + off, emb_h + off,
                                        SS, EE, FIN, FIN, FIN, EE, 0);
    }
    // 2. Layer-1 QKV (shared) -> fp16 only
    tgemm_h<<<tgrid(BB * PP, TE), 256>>>(emb_h, qw_h, qkv_b, (float*)0, qkv_h,
                                         BB * PP, TE, EE, EE, EE, TE, 0);
    // 3. attention -> fp16 attn_h
    attn1_kernel<<<dim3(NH, NWIN), 128>>>(qkv_h, attn_h);
    // 4. attn-out proj -> fp32 bufB
    tgemm_h<<<tgrid(NROW, EE), 256>>>(attn_h, aw_h, attn_out_b, bufB, (__half*)0,
                                      NROW, EE, EE, EE, EE, EE, 0);
    // 5. x1 = LN1(emb_window + bufB) -> bufA + x_h
    add_ln_kernel<<<NROW, 256>>>(bufB, emb, ln1_g, ln1_b, bufA, x_h, 1);
    // 6. FFN hidden (silu) -> fp16
    tgemm_h<<<tgrid(NROW, FF), 256>>>(x_h, f1w_h, ffn1_b, (float*)0, ffh_h,
                                      NROW, FF, EE, EE, EE, FF, 1);
    // 7. FFN out -> fp32 bufB
    tgemm_h<<<tgrid(NROW, EE), 256>>>(ffh_h, f2w_h, ffn2_b, bufB, (__half*)0,
                                      NROW, EE, FF, FF, FF, EE, 0);
    // 8. x2 = LN2(x1 + bufB) -> bufA + x_h
    add_ln_kernel<<<NROW, 256>>>(bufB, bufA, ln2_g, ln2_b, bufA, x_h, 0);

    // ---- Layer 2 (output pruned) ----
    // 9. gather last rows; Q only for last rows -> fp32 r2
    gather_last_kernel<<<(NWIN * EE + 255) / 256, 256>>>(bufA, xlast, xlast_h);
    tgemm_h<<<tgrid(NWIN, EE), 256>>>(xlast_h, qw_h + (size_t)TE * EE, qkv_b + TE,
                                      r2, (__half*)0, NWIN, EE, EE, EE, EE, EE, 0);
    // 10. KV for all rows -> fp16 kv2_h [NROW,512]
    tgemm_h<<<tgrid(NROW, 512), 256>>>(x_h, qw_h + (size_t)TE * EE + (size_t)EE * EE,
                                       qkv_b + TE + EE, (float*)0, kv2_h,
                                       NROW, 512, EE, EE, EE, 512, 0);
    // 11. attention -> fp16 r1_h
    attn2_kernel<<<dim3(NH, NWIN), 64>>>(r2, kv2_h, r1_h);
    // 12. proj -> fp32 r2
    tgemm_h<<<tgrid(NWIN, EE), 256>>>(r1_h, aw_h + (size_t)EE * EE, attn_out_b + EE,
                                      r2, (__half*)0, NWIN, EE, EE, EE, EE, EE, 0);
    // 13. y = LN1_l2(xlast + r2) -> r1 + r1_h
    add_ln_kernel<<<NWIN, 256>>>(r2, xlast, ln1_g + EE, ln1_b + EE, r1, r1_h, 0);
    // 14. h2 = silu(y @ W1^T) -> fp16 r3_h
    tgemm_h<<<tgrid(NWIN, FF), 256>>>(r1_h, f1w_h + (size_t)FF * EE, ffn1_b + FF,
                                      (float*)0, r3_h, NWIN, FF, EE, EE, EE, FF, 1);
    // 15. f2 -> fp32 r2
    tgemm_h<<<tgrid(NWIN, EE), 256>>>(r3_h, f2w_h + (size_t)EE * FF, ffn2_b + EE,
                                      r2, (__half*)0, NWIN, EE, FF, FF, FF, EE, 0);
    // 16. y2 = LN2_l2(y + f2) -> r1
    add_ln_kernel<<<NWIN, 256>>>(r2, r1, ln2_g + EE, ln2_b + EE, r1, (__half*)0, 0);
    // 17. head -> d_out
    head_kernel<<<(NWIN * OUTD + 255) / 256, 256>>>(r1, head_w, head_b, out);
}